// round 8
// baseline (speedup 1.0000x reference)
#include <cuda_runtime.h>
#include <cuda_bf16.h>
#include <math.h>
#include <stdint.h>

#define Nn 50000
#define Ee 800000
#define Gg 512
#define NSCAN_BLK 196          // ceil(50000/256)

// weight pack region offsets (elements)
#define BOFF1 0          // L1: 512 x 128
#define BOFF2 65536      // L2: 256 x 256
#define BOFF3 131072     // L3: 256 x 128
#define BTOT  163840

// ---------------- scratch ----------------
__device__ __align__(256) float g_H[Nn * 256];
__device__ __align__(256) float g_R[Nn * 256];
__device__ __align__(256) float g_asrc[Nn * 8];
__device__ __align__(256) float g_adst[Nn * 8];
__device__ __align__(256) float g_cnt[Gg];
// bf16 hi/lo split buffers
__device__ __align__(256) __nv_bfloat16 g_Ahi[Nn * 256];
__device__ __align__(256) __nv_bfloat16 g_Alo[Nn * 256];
__device__ __align__(256) __nv_bfloat16 g_Bhi[BTOT];
__device__ __align__(256) __nv_bfloat16 g_Blo[BTOT];
// CSR
__device__ int g_deg[Nn];
__device__ int g_off[Nn];
__device__ int g_cur[Nn];
__device__ int g_srcs[Ee];
__device__ int g_bsum[256];

__device__ __forceinline__ float lrelu(float x) { return x > 0.0f ? x : 0.2f * x; }
__device__ __forceinline__ void red4(float* p, float4 v) {
    atomicAdd(reinterpret_cast<float4*>(p), v);
}

// =========================== CSR build ===========================
__global__ void k_zero_deg() {
    int i = blockIdx.x * blockDim.x + threadIdx.x;
    if (i < Nn) g_deg[i] = 0;
}
__global__ void k_hist(const int* __restrict__ ei) {
    int e = blockIdx.x * blockDim.x + threadIdx.x;
    if (e < Ee) atomicAdd(&g_deg[ei[Ee + e]], 1);
}
__global__ void k_scan1() {
    __shared__ int sh[256];
    int tid = threadIdx.x;
    int i = blockIdx.x * 256 + tid;
    int v = (i < Nn) ? g_deg[i] : 0;
    sh[tid] = v; __syncthreads();
    for (int off = 1; off < 256; off <<= 1) {
        int t = (tid >= off) ? sh[tid - off] : 0;
        __syncthreads();
        sh[tid] += t;
        __syncthreads();
    }
    if (i < Nn) g_off[i] = sh[tid] - v;
    if (tid == 255) g_bsum[blockIdx.x] = sh[255];
}
__global__ void k_scan2() {
    __shared__ int sh[256];
    int tid = threadIdx.x;
    int v = (tid < NSCAN_BLK) ? g_bsum[tid] : 0;
    sh[tid] = v; __syncthreads();
    for (int off = 1; off < 256; off <<= 1) {
        int t = (tid >= off) ? sh[tid - off] : 0;
        __syncthreads();
        sh[tid] += t;
        __syncthreads();
    }
    if (tid < NSCAN_BLK) g_bsum[tid] = sh[tid] - v;
}
__global__ void k_scan3() {
    int i = blockIdx.x * blockDim.x + threadIdx.x;
    if (i < Nn) {
        g_off[i] += g_bsum[i >> 8];
        g_cur[i] = 0;
    }
}
__global__ void k_scatter(const int* __restrict__ ei) {
    int e = blockIdx.x * blockDim.x + threadIdx.x;
    if (e >= Ee) return;
    int d = ei[Ee + e];
    int pos = g_off[d] + atomicAdd(&g_cur[d], 1);
    g_srcs[pos] = ei[e];
}

// =========== fused: fp32->bf16 hi/lo split of x  +  prepack of layer-1 weights ===========
#define CVT4_L1 (Nn * 128 / 4)
__global__ void k_cvt_pre(const float* __restrict__ X,
                          __nv_bfloat16* __restrict__ hi, __nv_bfloat16* __restrict__ lo,
                          const float* __restrict__ W, const float* __restrict__ pw) {
    int idx = blockIdx.x * blockDim.x + threadIdx.x;
    if (idx < CVT4_L1) {
        float4 v = reinterpret_cast<const float4*>(X)[idx];
        __nv_bfloat16 h0 = __float2bfloat16(v.x), h1 = __float2bfloat16(v.y);
        __nv_bfloat16 h2 = __float2bfloat16(v.z), h3 = __float2bfloat16(v.w);
        __nv_bfloat16 l0 = __float2bfloat16(v.x - __bfloat162float(h0));
        __nv_bfloat16 l1 = __float2bfloat16(v.y - __bfloat162float(h1));
        __nv_bfloat16 l2 = __float2bfloat16(v.z - __bfloat162float(h2));
        __nv_bfloat16 l3 = __float2bfloat16(v.w - __bfloat162float(h3));
        __nv_bfloat162* H2 = reinterpret_cast<__nv_bfloat162*>(hi);
        __nv_bfloat162* L2 = reinterpret_cast<__nv_bfloat162*>(lo);
        H2[idx * 2]     = __nv_bfloat162(h0, h1);
        H2[idx * 2 + 1] = __nv_bfloat162(h2, h3);
        L2[idx * 2]     = __nv_bfloat162(l0, l1);
        L2[idx * 2 + 1] = __nv_bfloat162(l2, l3);
    } else {
        int j = idx - CVT4_L1;                 // 0 .. 512*128-1
        if (j < 512 * 128) {
            const int K = 128, Dhalf = 256;
            int n = j / K, k = j - n * K;
            float w = (n < Dhalf) ? W[(size_t)k * Dhalf + n]
                                  : pw[(size_t)k * Dhalf + (n - Dhalf)];
            __nv_bfloat16 h = __float2bfloat16(w);
            g_Bhi[BOFF1 + j] = h;
            g_Blo[BOFF1 + j] = __float2bfloat16(w - __bfloat162float(h));
        }
    }
}

// prepack (layers 2/3, on side stream)
__global__ void k_prepack(const float* __restrict__ W, const float* __restrict__ pw,
                          int K, int Dhalf, int boff) {
    int idx = blockIdx.x * blockDim.x + threadIdx.x;
    int Ncat = 2 * Dhalf;
    if (idx >= Ncat * K) return;
    int n = idx / K, k = idx - n * K;
    float w = (n < Dhalf) ? W[(size_t)k * Dhalf + n] : pw[(size_t)k * Dhalf + (n - Dhalf)];
    __nv_bfloat16 h = __float2bfloat16(w);
    g_Bhi[boff + idx] = h;
    g_Blo[boff + idx] = __float2bfloat16(w - __bfloat162float(h));
}

// =========================== HMMA GEMM (cp.async + ldmatrix) ===========================
#define SROW 40
#define STAGE_BYTES 40960
#define OFF_AHI 0
#define OFF_ALO 10240
#define OFF_BHI 20480
#define OFF_BLO 30720

__device__ __forceinline__ void mma16816(float* d, const uint32_t* a, const uint32_t* b) {
    asm volatile(
        "mma.sync.aligned.m16n8k16.row.col.f32.bf16.bf16.f32 "
        "{%0,%1,%2,%3}, {%4,%5,%6,%7}, {%8,%9}, {%0,%1,%2,%3};"
        : "+f"(d[0]), "+f"(d[1]), "+f"(d[2]), "+f"(d[3])
        : "r"(a[0]), "r"(a[1]), "r"(a[2]), "r"(a[3]), "r"(b[0]), "r"(b[1]));
}

__device__ __forceinline__ void ldsm4(uint32_t* r, uint32_t addr) {
    asm volatile("ldmatrix.sync.aligned.m8n8.x4.shared.b16 {%0,%1,%2,%3}, [%4];"
                 : "=r"(r[0]), "=r"(r[1]), "=r"(r[2]), "=r"(r[3]) : "r"(addr));
}

__device__ __forceinline__ uint32_t smem_u32(const void* p) {
    uint32_t a;
    asm("{ .reg .u64 t; cvta.to.shared.u64 t, %1; cvt.u32.u64 %0, t; }" : "=r"(a) : "l"(p));
    return a;
}

__device__ __forceinline__ void cp16(uint32_t dst, const void* src, bool ok) {
    asm volatile(
        "{\n\t.reg .pred p;\n\tsetp.ne.u32 p, %2, 0;\n\t"
        "@p cp.async.cg.shared.global [%0], [%1], 16;\n\t"
        "@!p cp.async.cg.shared.global [%0], [%1], 16, 0;\n\t}"
        :: "r"(dst), "l"(src), "r"((unsigned)ok) : "memory");
}

// Hh > 0 : C=32 fused per-head scores (warp column slice = one head)
// Hh == -1: layer-3 scores (single head, C=128) via smem cross-warp reduce
// Hh == 0 : no score epilogue
__global__ __launch_bounds__(256) void k_hgemm(
        const __nv_bfloat16* __restrict__ Ahi, const __nv_bfloat16* __restrict__ Alo,
        const __nv_bfloat16* __restrict__ Bhi, const __nv_bfloat16* __restrict__ Blo,
        const float* __restrict__ pb, float* __restrict__ Hout, float* __restrict__ Rout,
        const float* __restrict__ asv, const float* __restrict__ adv,
        int K, int Dhalf, int Hh) {
    extern __shared__ __align__(16) char smem[];
    const uint32_t sbase = smem_u32(smem);

    const int tid = threadIdx.x;
    const int wid = tid >> 5, lane = tid & 31;
    const int row0 = blockIdx.y * 128;
    const int n0 = blockIdx.x * 128;
    const int KC = K >> 5;
    const int wr = wid >> 2;
    const int wc = wid & 3;
    const int tr = lane >> 2;
    const int tc = (lane & 3) * 2;

    const int lr = tid >> 2;
    const int lk = (tid & 3) * 8;

    // per-lane ldmatrix base offsets (bytes within a stage's A/B region)
    const uint32_t a_base = (uint32_t)(((wr * 64 + (lane & 15)) * SROW + (lane >> 4) * 8) * 2);
    const int bt = lane >> 3;
    const uint32_t b_base = (uint32_t)((((wc * 32 + (bt >> 1) * 8 + (lane & 7))) * SROW + (bt & 1) * 8) * 2);

    float acc[4][4][4];
#pragma unroll
    for (int mi = 0; mi < 4; mi++)
#pragma unroll
        for (int ni = 0; ni < 4; ni++)
#pragma unroll
            for (int q = 0; q < 4; q++) acc[mi][ni][q] = 0.f;

    auto load_stage = [&](int stage, int kc) {
        const uint32_t sb = sbase + stage * STAGE_BYTES;
        const int kofs = kc * 32 + lk;
#pragma unroll
        for (int it = 0; it < 2; it++) {
            int r = lr + it * 64;
            uint32_t so = (uint32_t)(r * SROW + lk) * 2;
            int ar = row0 + r;
            bool ok = ar < Nn;
            int arc = ok ? ar : 0;
            cp16(sb + OFF_AHI + so, Ahi + (size_t)arc * K + kofs, ok);
            cp16(sb + OFF_ALO + so, Alo + (size_t)arc * K + kofs, ok);
            cp16(sb + OFF_BHI + so, Bhi + (size_t)(n0 + r) * K + kofs, true);
            cp16(sb + OFF_BLO + so, Blo + (size_t)(n0 + r) * K + kofs, true);
        }
        asm volatile("cp.async.commit_group;" ::: "memory");
    };

    load_stage(0, 0);

    for (int kc = 0; kc < KC; kc++) {
        const int stage = kc & 1;
        if (kc + 1 < KC) {
            load_stage((kc + 1) & 1, kc + 1);
            asm volatile("cp.async.wait_group 1;" ::: "memory");
        } else {
            asm volatile("cp.async.wait_group 0;" ::: "memory");
        }
        __syncthreads();

        const uint32_t sb = sbase + stage * STAGE_BYTES;

#pragma unroll
        for (int ks = 0; ks < 2; ks++) {
            const uint32_t kbB = (uint32_t)(ks * 16 * 2);   // k-offset in bytes
            uint32_t a_f[4][4], bh[8], bl[8];
#pragma unroll
            for (int p = 0; p < 2; p++) {
                ldsm4(bh + p * 4, sb + OFF_BHI + b_base + p * (16 * SROW * 2) + kbB);
                ldsm4(bl + p * 4, sb + OFF_BLO + b_base + p * (16 * SROW * 2) + kbB);
            }
#pragma unroll
            for (int mi = 0; mi < 4; mi++)
                ldsm4(a_f[mi], sb + OFF_AHI + a_base + mi * (16 * SROW * 2) + kbB);
#pragma unroll
            for (int mi = 0; mi < 4; mi++)
#pragma unroll
                for (int ni = 0; ni < 4; ni++) {
                    mma16816(acc[mi][ni], a_f[mi], bh + ni * 2);
                    mma16816(acc[mi][ni], a_f[mi], bl + ni * 2);
                }
#pragma unroll
            for (int mi = 0; mi < 4; mi++)
                ldsm4(a_f[mi], sb + OFF_ALO + a_base + mi * (16 * SROW * 2) + kbB);
#pragma unroll
            for (int mi = 0; mi < 4; mi++)
#pragma unroll
                for (int ni = 0; ni < 4; ni++)
                    mma16816(acc[mi][ni], a_f[mi], bh + ni * 2);
        }
        __syncthreads();
    }

    const bool isR = (n0 >= Dhalf);
    float* dst = isR ? Rout : Hout;
    const int cbase = (isR ? (n0 - Dhalf) : n0) + wc * 32;
#pragma unroll
    for (int mi = 0; mi < 4; mi++) {
        int r1 = row0 + wr * 64 + mi * 16 + tr;
        int r2 = r1 + 8;
#pragma unroll
        for (int ni = 0; ni < 4; ni++) {
            int cc = cbase + ni * 8 + tc;
            float bx = 0.f, by = 0.f;
            if (isR) { bx = pb[cc]; by = pb[cc + 1]; }
            if (r1 < Nn) {
                float2 o = make_float2(acc[mi][ni][0] + bx, acc[mi][ni][1] + by);
                *reinterpret_cast<float2*>(dst + (size_t)r1 * Dhalf + cc) = o;
            }
            if (r2 < Nn) {
                float2 o = make_float2(acc[mi][ni][2] + bx, acc[mi][ni][3] + by);
                *reinterpret_cast<float2*>(dst + (size_t)r2 * Dhalf + cc) = o;
            }
        }
    }

    // ---- fused attention scores ----
    if (Hh != 0 && !isR) {
        // slice of a_src/a_dst for this warp's 32 columns (flat view)
        const float* as_sl = asv + n0 + wc * 32;
        const float* ad_sl = adv + n0 + wc * 32;
        float as_c[8], ad_c[8];
#pragma unroll
        for (int ni = 0; ni < 4; ni++) {
            int c0 = ni * 8 + tc;
            as_c[ni * 2]     = as_sl[c0];
            as_c[ni * 2 + 1] = as_sl[c0 + 1];
            ad_c[ni * 2]     = ad_sl[c0];
            ad_c[ni * 2 + 1] = ad_sl[c0 + 1];
        }
        float* sAS = reinterpret_cast<float*>(smem);        // [128]
        float* sAD = reinterpret_cast<float*>(smem) + 128;  // [128]
        if (Hh < 0) {
            if (tid < 128) { sAS[tid] = 0.f; sAD[tid] = 0.f; }
            __syncthreads();
        }
#pragma unroll
        for (int mi = 0; mi < 4; mi++) {
            int lrow1 = wr * 64 + mi * 16 + tr;
            int lrow2 = lrow1 + 8;
            float as1 = 0.f, ad1 = 0.f, as2 = 0.f, ad2 = 0.f;
#pragma unroll
            for (int ni = 0; ni < 4; ni++) {
                as1 = fmaf(acc[mi][ni][0], as_c[ni * 2], fmaf(acc[mi][ni][1], as_c[ni * 2 + 1], as1));
                ad1 = fmaf(acc[mi][ni][0], ad_c[ni * 2], fmaf(acc[mi][ni][1], ad_c[ni * 2 + 1], ad1));
                as2 = fmaf(acc[mi][ni][2], as_c[ni * 2], fmaf(acc[mi][ni][3], as_c[ni * 2 + 1], as2));
                ad2 = fmaf(acc[mi][ni][2], ad_c[ni * 2], fmaf(acc[mi][ni][3], ad_c[ni * 2 + 1], ad2));
            }
#pragma unroll
            for (int o = 1; o < 4; o <<= 1) {
                as1 += __shfl_xor_sync(0xFFFFFFFFu, as1, o);
                ad1 += __shfl_xor_sync(0xFFFFFFFFu, ad1, o);
                as2 += __shfl_xor_sync(0xFFFFFFFFu, as2, o);
                ad2 += __shfl_xor_sync(0xFFFFFFFFu, ad2, o);
            }
            if ((lane & 3) == 0) {
                if (Hh > 0) {
                    const int head = (n0 >> 5) + wc;
                    int r1 = row0 + lrow1, r2 = row0 + lrow2;
                    if (r1 < Nn) { g_asrc[r1 * Hh + head] = as1; g_adst[r1 * Hh + head] = ad1; }
                    if (r2 < Nn) { g_asrc[r2 * Hh + head] = as2; g_adst[r2 * Hh + head] = ad2; }
                } else {
                    atomicAdd(&sAS[lrow1], as1); atomicAdd(&sAD[lrow1], ad1);
                    atomicAdd(&sAS[lrow2], as2); atomicAdd(&sAD[lrow2], ad2);
                }
            }
        }
        if (Hh < 0) {
            __syncthreads();
            if (tid < 128 && row0 + tid < Nn) {
                g_asrc[row0 + tid] = sAS[tid];
                g_adst[row0 + tid] = sAD[tid];
            }
        }
    }
}

// ============ fused GAT gather + softmax + bias + LN + residual + ELU ============
template<int Hh, int C, bool WB16, bool POOL>
__global__ __launch_bounds__(256) void k_gat(
        const float* __restrict__ H, const float* __restrict__ R,
        const float* __restrict__ bias, const float* __restrict__ gam,
        const float* __restrict__ bet,
        __nv_bfloat16* __restrict__ Ohi, __nv_bfloat16* __restrict__ Olo,
        const int* __restrict__ batch, float* __restrict__ out) {
    constexpr int D = Hh * C;
    constexpr int NF4 = D / 4;
    constexpr int IT = NF4 / 32;
    constexpr int C4 = C / 4;

    int n = blockIdx.x * (blockDim.x >> 5) + (threadIdx.x >> 5);
    if (n >= Nn) return;
    int lane = threadIdx.x & 31;

    float adst_l = (lane < Hh) ? g_adst[n * Hh + lane] : 0.f;
    float denom_l = 0.f;
    float4 acc[IT];
#pragma unroll
    for (int t = 0; t < IT; t++) acc[t] = make_float4(0.f, 0.f, 0.f, 0.f);

    const float4* H4 = reinterpret_cast<const float4*>(H);

    int beg = g_off[n];
    int deg = g_deg[n];
    int s_next = (deg > 0) ? g_srcs[beg] : n;

    for (int e = 0; e <= deg; e++) {
        int s = s_next;
        s_next = (e + 1 < deg) ? g_srcs[beg + e + 1] : n;
        float w_l = 0.f;
        if (lane < Hh) {
            float ev = lrelu(g_asrc[s * Hh + lane] + adst_l);
            w_l = __expf(ev);
            denom_l += w_l;
        }
#pragma unroll
        for (int t = 0; t < IT; t++) {
            int j = lane + t * 32;
            float wj = __shfl_sync(0xFFFFFFFFu, w_l, j / C4);
            float4 hv = H4[(size_t)s * NF4 + j];
            acc[t].x = fmaf(wj, hv.x, acc[t].x);
            acc[t].y = fmaf(wj, hv.y, acc[t].y);
            acc[t].z = fmaf(wj, hv.z, acc[t].z);
            acc[t].w = fmaf(wj, hv.w, acc[t].w);
        }
    }

    float vals[IT * 4];
    float s1 = 0.f, s2 = 0.f;
    const float4* B4 = reinterpret_cast<const float4*>(bias);
#pragma unroll
    for (int t = 0; t < IT; t++) {
        int j = lane + t * 32;
        float dj = __shfl_sync(0xFFFFFFFFu, denom_l, j / C4) + 1e-16f;
        float inv = 1.0f / dj;
        float4 bv = B4[j];
        float4 v = make_float4(fmaf(acc[t].x, inv, bv.x), fmaf(acc[t].y, inv, bv.y),
                               fmaf(acc[t].z, inv, bv.z), fmaf(acc[t].w, inv, bv.w));
        vals[t * 4 + 0] = v.x; vals[t * 4 + 1] = v.y;
        vals[t * 4 + 2] = v.z; vals[t * 4 + 3] = v.w;
        s1 += v.x + v.y + v.z + v.w;
        s2 = fmaf(v.x, v.x, fmaf(v.y, v.y, fmaf(v.z, v.z, fmaf(v.w, v.w, s2))));
    }
#pragma unroll
    for (int o = 16; o > 0; o >>= 1) {
        s1 += __shfl_xor_sync(0xFFFFFFFFu, s1, o);
        s2 += __shfl_xor_sync(0xFFFFFFFFu, s2, o);
    }
    float mean = s1 / (float)D;
    float var = s2 / (float)D - mean * mean;
    float inv = rsqrtf(var + 1e-5f);

    const float4* G4 = reinterpret_cast<const float4*>(gam);
    const float4* E4 = reinterpret_cast<const float4*>(bet);
    const float4* R4 = reinterpret_cast<const float4*>(R);
#pragma unroll
    for (int t = 0; t < IT; t++) {
        int j = lane + t * 32;
        float4 gv = G4[j], ev = E4[j], rv = R4[(size_t)n * NF4 + j];
        float x0 = (vals[t * 4 + 0] - mean) * inv * gv.x + ev.x + rv.x;
        float x1 = (vals[t * 4 + 1] - mean) * inv * gv.y + ev.y + rv.y;
        float x2 = (vals[t * 4 + 2] - mean) * inv * gv.z + ev.z + rv.z;
        float x3 = (vals[t * 4 + 3] - mean) * inv * gv.w + ev.w + rv.w;
        float4 o;
        o.x = x0 > 0.f ? x0 : expm1f(x0);
        o.y = x1 > 0.f ? x1 : expm1f(x1);
        o.z = x2 > 0.f ? x2 : expm1f(x2);
        o.w = x3 > 0.f ? x3 : expm1f(x3);
        if (WB16) {
            __nv_bfloat16 h0 = __float2bfloat16(o.x), h1 = __float2bfloat16(o.y);
            __nv_bfloat16 h2 = __float2bfloat16(o.z), h3 = __float2bfloat16(o.w);
            __nv_bfloat16 l0 = __float2bfloat16(o.x - __bfloat162float(h0));
            __nv_bfloat16 l1 = __float2bfloat16(o.y - __bfloat162float(h1));
            __nv_bfloat16 l2 = __float2bfloat16(o.z - __bfloat162float(h2));
            __nv_bfloat16 l3 = __float2bfloat16(o.w - __bfloat162float(h3));
            __nv_bfloat162* OH = reinterpret_cast<__nv_bfloat162*>(Ohi + (size_t)n * D + j * 4);
            __nv_bfloat162* OL = reinterpret_cast<__nv_bfloat162*>(Olo + (size_t)n * D + j * 4);
            OH[0] = __nv_bfloat162(h0, h1);
            OH[1] = __nv_bfloat162(h2, h3);
            OL[0] = __nv_bfloat162(l0, l1);
            OL[1] = __nv_bfloat162(l2, l3);
        } else if (POOL) {
            int b = batch[n];
            red4(&out[b * 128 + j * 4], o);
            if (j == 0) atomicAdd(&g_cnt[b], 1.0f);
        }
    }
}

// =========================== pooling finalize ===========================
__global__ void k_pool_zero(float* __restrict__ out) {
    int idx = blockIdx.x * blockDim.x + threadIdx.x;
    if (idx < Gg * 128) out[idx] = 0.f;
    if (idx < Gg) g_cnt[idx] = 0.f;
}
__global__ void k_pool_div(float* __restrict__ out) {
    int idx = blockIdx.x * blockDim.x + threadIdx.x;
    if (idx >= Gg * 128) return;
    out[idx] /= fmaxf(g_cnt[idx >> 7], 1.0f);
}

// =========================== host ===========================
extern "C" void kernel_launch(void* const* d_in, const int* in_sizes, int n_in,
                              void* d_out, int out_size) {
    const float* x   = (const float*)d_in[0];
    const int* ei    = (const int*)d_in[1];
    const int* batch = (const int*)d_in[2];
    const float* W1 = (const float*)d_in[3],  *as1 = (const float*)d_in[4],
               *ad1 = (const float*)d_in[5],  *b1  = (const float*)d_in[6],
               *g1  = (const float*)d_in[7],  *be1 = (const float*)d_in[8],
               *pw1 = (const float*)d_in[9],  *pb1 = (const float*)d_in[10];
    const float* W2 = (const float*)d_in[11], *as2 = (const float*)d_in[12],
               *ad2 = (const float*)d_in[13], *b2  = (const float*)d_in[14],
               *g2  = (const float*)d_in[15], *be2 = (const float*)d_in[16],
               *pw2 = (const float*)d_in[17], *pb2 = (const float*)d_in[18];
    const float* W3 = (const float*)d_in[19], *as3 = (const float*)d_in[20],
               *ad3 = (const float*)d_in[21], *b3  = (const float*)d_in[22],
               *g3  = (const float*)d_in[23], *be3 = (const float*)d_in[24],
               *pw3 = (const float*)d_in[25], *pb3 = (const float*)d_in[26];
    float* out = (float*)d_out;

    void *pH_, *pR_, *pAhi_, *pAlo_, *pBhi_, *pBlo_;
    cudaGetSymbolAddress(&pH_,  g_H);
    cudaGetSymbolAddress(&pR_,  g_R);
    cudaGetSymbolAddress(&pAhi_, g_Ahi);
    cudaGetSymbolAddress(&pAlo_, g_Alo);
    cudaGetSymbolAddress(&pBhi_, g_Bhi);
    cudaGetSymbolAddress(&pBlo_, g_Blo);
    float* pH  = (float*)pH_;
    float* pR  = (float*)pR_;
    __nv_bfloat16* pAhi = (__nv_bfloat16*)pAhi_;
    __nv_bfloat16* pAlo = (__nv_bfloat16*)pAlo_;
    __nv_bfloat16* pBhi = (__nv_bfloat16*)pBhi_;
    __nv_bfloat16* pBlo = (__nv_bfloat16*)pBlo_;

    cudaFuncSetAttribute(k_hgemm, cudaFuncAttributeMaxDynamicSharedMemorySize, 2 * STAGE_BYTES);

    static cudaStream_t s2 = nullptr;
    static cudaEvent_t evFork = nullptr, evSide = nullptr;
    if (!s2) {
        cudaStreamCreateWithFlags(&s2, cudaStreamNonBlocking);
        cudaEventCreateWithFlags(&evFork, cudaEventDisableTiming);
        cudaEventCreateWithFlags(&evSide, cudaEventDisableTiming);
    }

    const int TB = 256;
    const int MT = (Nn + 127) / 128;

    // ---- fork: side stream does CSR build + prepack L2/L3 + pool zero ----
    cudaEventRecord(evFork, 0);
    cudaStreamWaitEvent(s2, evFork, 0);

    k_zero_deg<<<(Nn + TB - 1) / TB, TB, 0, s2>>>();
    k_hist<<<(Ee + TB - 1) / TB, TB, 0, s2>>>(ei);
    k_scan1<<<NSCAN_BLK, 256, 0, s2>>>();
    k_scan2<<<1, 256, 0, s2>>>();
    k_scan3<<<(Nn + TB - 1) / TB, TB, 0, s2>>>();
    k_scatter<<<(Ee + TB - 1) / TB, TB, 0, s2>>>(ei);
    k_prepack<<<(2 * 128 * 256 + TB - 1) / TB, TB, 0, s2>>>(W2, pw2, 256, 128, BOFF2);
    k_prepack<<<(2 * 128 * 128 + TB - 1) / TB, TB, 0, s2>>>(W3, pw3, 128, 128, BOFF3);
    k_pool_zero<<<(Gg * 128 + TB - 1) / TB, TB, 0, s2>>>(out);
    cudaEventRecord(evSide, s2);

    // ---- main stream: layer 1 (cvt + prepack1 fused; scores fused into GEMM) ----
    k_cvt_pre<<<(CVT4_L1 + 512 * 128 + TB - 1) / TB, TB>>>(x, pAhi, pAlo, W1, pw1);
    k_hgemm<<<dim3(4, MT), 256, 2 * STAGE_BYTES>>>(pAhi, pAlo, pBhi + BOFF1, pBlo + BOFF1,
                                                   pb1, pH, pR, as1, ad1, 128, 256, 8);

    cudaStreamWaitEvent(0, evSide, 0);

    k_gat<8, 32, true, false><<<(Nn * 32 + TB - 1) / TB, TB>>>(pH, pR, b1, g1, be1,
                                                               pAhi, pAlo, nullptr, nullptr);

    // ---- Layer 2 (scores fused) ----
    k_hgemm<<<dim3(2, MT), 256, 2 * STAGE_BYTES>>>(pAhi, pAlo, pBhi + BOFF2, pBlo + BOFF2,
                                                   pb2, pH, pR, as2, ad2, 256, 128, 4);
    k_gat<4, 32, true, false><<<(Nn * 32 + TB - 1) / TB, TB>>>(pH, pR, b2, g2, be2,
                                                               pAhi, pAlo, nullptr, nullptr);

    // ---- Layer 3 (scores fused via smem reduce; pool fused into gat) ----
    k_hgemm<<<dim3(2, MT), 256, 2 * STAGE_BYTES>>>(pAhi, pAlo, pBhi + BOFF3, pBlo + BOFF3,
                                                   pb3, pH, pR, as3, ad3, 128, 128, -1);
    k_gat<1, 128, false, true><<<(Nn * 32 + TB - 1) / TB, TB>>>(pH, pR, b3, g3, be3,
                                                                nullptr, nullptr, batch, out);

    k_pool_div<<<(Gg * 128 + TB - 1) / TB, TB>>>(out);
}

// round 9
// speedup vs baseline: 1.1082x; 1.1082x over previous
#include <cuda_runtime.h>
#include <cuda_bf16.h>
#include <cuda_fp16.h>
#include <math.h>
#include <stdint.h>

#define Nn 50000
#define Ee 800000
#define Gg 512
#define NSCAN_BLK 196          // ceil(50000/256)

// weight pack region offsets (elements)
#define BOFF1 0          // L1: 512 x 128
#define BOFF2 65536      // L2: 256 x 256
#define BOFF3 131072     // L3: 256 x 128
#define BTOT  163840

// ---------------- scratch ----------------
__device__ __align__(256) __half g_H[Nn * 256];    // GAT features, fp16 (gather traffic /2)
__device__ __align__(256) float g_R[Nn * 256];
__device__ __align__(256) float g_asrc[Nn * 8];
__device__ __align__(256) float g_adst[Nn * 8];
__device__ __align__(256) float g_cnt[Gg];
// bf16 hi/lo split buffers
__device__ __align__(256) __nv_bfloat16 g_Ahi[Nn * 256];
__device__ __align__(256) __nv_bfloat16 g_Alo[Nn * 256];
__device__ __align__(256) __nv_bfloat16 g_Bhi[BTOT];
__device__ __align__(256) __nv_bfloat16 g_Blo[BTOT];
// CSR
__device__ int g_deg[Nn];
__device__ int g_off[Nn];
__device__ int g_cur[Nn];
__device__ int g_srcs[Ee];
__device__ int g_bsum[256];

__device__ __forceinline__ float lrelu(float x) { return x > 0.0f ? x : 0.2f * x; }
__device__ __forceinline__ void red4(float* p, float4 v) {
    atomicAdd(reinterpret_cast<float4*>(p), v);
}

// =========================== CSR build ===========================
__global__ void k_zero_deg() {
    int i = blockIdx.x * blockDim.x + threadIdx.x;
    if (i < Nn) g_deg[i] = 0;
}
__global__ void k_hist(const int* __restrict__ ei) {
    int e = blockIdx.x * blockDim.x + threadIdx.x;
    if (e < Ee) atomicAdd(&g_deg[ei[Ee + e]], 1);
}
__global__ void k_scan1() {
    __shared__ int sh[256];
    int tid = threadIdx.x;
    int i = blockIdx.x * 256 + tid;
    int v = (i < Nn) ? g_deg[i] : 0;
    sh[tid] = v; __syncthreads();
    for (int off = 1; off < 256; off <<= 1) {
        int t = (tid >= off) ? sh[tid - off] : 0;
        __syncthreads();
        sh[tid] += t;
        __syncthreads();
    }
    if (i < Nn) g_off[i] = sh[tid] - v;
    if (tid == 255) g_bsum[blockIdx.x] = sh[255];
}
__global__ void k_scan2() {
    __shared__ int sh[256];
    int tid = threadIdx.x;
    int v = (tid < NSCAN_BLK) ? g_bsum[tid] : 0;
    sh[tid] = v; __syncthreads();
    for (int off = 1; off < 256; off <<= 1) {
        int t = (tid >= off) ? sh[tid - off] : 0;
        __syncthreads();
        sh[tid] += t;
        __syncthreads();
    }
    if (tid < NSCAN_BLK) g_bsum[tid] = sh[tid] - v;
}
__global__ void k_scan3() {
    int i = blockIdx.x * blockDim.x + threadIdx.x;
    if (i < Nn) {
        g_off[i] += g_bsum[i >> 8];
        g_cur[i] = 0;
    }
}
__global__ void k_scatter(const int* __restrict__ ei) {
    int e = blockIdx.x * blockDim.x + threadIdx.x;
    if (e >= Ee) return;
    int d = ei[Ee + e];
    int pos = g_off[d] + atomicAdd(&g_cur[d], 1);
    g_srcs[pos] = ei[e];
}

// =========== fused: fp32->bf16 hi/lo split of x  +  prepack of layer-1 weights ===========
#define CVT4_L1 (Nn * 128 / 4)
__global__ void k_cvt_pre(const float* __restrict__ X,
                          __nv_bfloat16* __restrict__ hi, __nv_bfloat16* __restrict__ lo,
                          const float* __restrict__ W, const float* __restrict__ pw) {
    int idx = blockIdx.x * blockDim.x + threadIdx.x;
    if (idx < CVT4_L1) {
        float4 v = reinterpret_cast<const float4*>(X)[idx];
        __nv_bfloat16 h0 = __float2bfloat16(v.x), h1 = __float2bfloat16(v.y);
        __nv_bfloat16 h2 = __float2bfloat16(v.z), h3 = __float2bfloat16(v.w);
        __nv_bfloat16 l0 = __float2bfloat16(v.x - __bfloat162float(h0));
        __nv_bfloat16 l1 = __float2bfloat16(v.y - __bfloat162float(h1));
        __nv_bfloat16 l2 = __float2bfloat16(v.z - __bfloat162float(h2));
        __nv_bfloat16 l3 = __float2bfloat16(v.w - __bfloat162float(h3));
        __nv_bfloat162* H2 = reinterpret_cast<__nv_bfloat162*>(hi);
        __nv_bfloat162* L2 = reinterpret_cast<__nv_bfloat162*>(lo);
        H2[idx * 2]     = __nv_bfloat162(h0, h1);
        H2[idx * 2 + 1] = __nv_bfloat162(h2, h3);
        L2[idx * 2]     = __nv_bfloat162(l0, l1);
        L2[idx * 2 + 1] = __nv_bfloat162(l2, l3);
    } else {
        int j = idx - CVT4_L1;                 // 0 .. 512*128-1
        if (j < 512 * 128) {
            const int K = 128, Dhalf = 256;
            int n = j / K, k = j - n * K;
            float w = (n < Dhalf) ? W[(size_t)k * Dhalf + n]
                                  : pw[(size_t)k * Dhalf + (n - Dhalf)];
            __nv_bfloat16 h = __float2bfloat16(w);
            g_Bhi[BOFF1 + j] = h;
            g_Blo[BOFF1 + j] = __float2bfloat16(w - __bfloat162float(h));
        }
    }
}

// prepack (layers 2/3, on side stream)
__global__ void k_prepack(const float* __restrict__ W, const float* __restrict__ pw,
                          int K, int Dhalf, int boff) {
    int idx = blockIdx.x * blockDim.x + threadIdx.x;
    int Ncat = 2 * Dhalf;
    if (idx >= Ncat * K) return;
    int n = idx / K, k = idx - n * K;
    float w = (n < Dhalf) ? W[(size_t)k * Dhalf + n] : pw[(size_t)k * Dhalf + (n - Dhalf)];
    __nv_bfloat16 h = __float2bfloat16(w);
    g_Bhi[boff + idx] = h;
    g_Blo[boff + idx] = __float2bfloat16(w - __bfloat162float(h));
}

// =========================== HMMA GEMM (cp.async + ldmatrix) ===========================
#define SROW 40
#define STAGE_BYTES 40960
#define OFF_AHI 0
#define OFF_ALO 10240
#define OFF_BHI 20480
#define OFF_BLO 30720

__device__ __forceinline__ void mma16816(float* d, const uint32_t* a, const uint32_t* b) {
    asm volatile(
        "mma.sync.aligned.m16n8k16.row.col.f32.bf16.bf16.f32 "
        "{%0,%1,%2,%3}, {%4,%5,%6,%7}, {%8,%9}, {%0,%1,%2,%3};"
        : "+f"(d[0]), "+f"(d[1]), "+f"(d[2]), "+f"(d[3])
        : "r"(a[0]), "r"(a[1]), "r"(a[2]), "r"(a[3]), "r"(b[0]), "r"(b[1]));
}

__device__ __forceinline__ void ldsm4(uint32_t* r, uint32_t addr) {
    asm volatile("ldmatrix.sync.aligned.m8n8.x4.shared.b16 {%0,%1,%2,%3}, [%4];"
                 : "=r"(r[0]), "=r"(r[1]), "=r"(r[2]), "=r"(r[3]) : "r"(addr));
}

__device__ __forceinline__ uint32_t smem_u32(const void* p) {
    uint32_t a;
    asm("{ .reg .u64 t; cvta.to.shared.u64 t, %1; cvt.u32.u64 %0, t; }" : "=r"(a) : "l"(p));
    return a;
}

__device__ __forceinline__ void cp16(uint32_t dst, const void* src, bool ok) {
    asm volatile(
        "{\n\t.reg .pred p;\n\tsetp.ne.u32 p, %2, 0;\n\t"
        "@p cp.async.cg.shared.global [%0], [%1], 16;\n\t"
        "@!p cp.async.cg.shared.global [%0], [%1], 16, 0;\n\t}"
        :: "r"(dst), "l"(src), "r"((unsigned)ok) : "memory");
}

// Hh > 0 : C=32 fused per-head scores (warp column slice = one head)
// Hh == -1: layer-3 scores (single head, C=128) via smem cross-warp reduce
__global__ __launch_bounds__(256) void k_hgemm(
        const __nv_bfloat16* __restrict__ Ahi, const __nv_bfloat16* __restrict__ Alo,
        const __nv_bfloat16* __restrict__ Bhi, const __nv_bfloat16* __restrict__ Blo,
        const float* __restrict__ pb, __half* __restrict__ Hout, float* __restrict__ Rout,
        const float* __restrict__ asv, const float* __restrict__ adv,
        int K, int Dhalf, int Hh) {
    extern __shared__ __align__(16) char smem[];
    const uint32_t sbase = smem_u32(smem);

    const int tid = threadIdx.x;
    const int wid = tid >> 5, lane = tid & 31;
    const int row0 = blockIdx.y * 128;
    const int n0 = blockIdx.x * 128;
    const int KC = K >> 5;
    const int wr = wid >> 2;
    const int wc = wid & 3;
    const int tr = lane >> 2;
    const int tc = (lane & 3) * 2;

    const int lr = tid >> 2;
    const int lk = (tid & 3) * 8;

    const uint32_t a_base = (uint32_t)(((wr * 64 + (lane & 15)) * SROW + (lane >> 4) * 8) * 2);
    const int bt = lane >> 3;
    const uint32_t b_base = (uint32_t)((((wc * 32 + (bt >> 1) * 8 + (lane & 7))) * SROW + (bt & 1) * 8) * 2);

    float acc[4][4][4];
#pragma unroll
    for (int mi = 0; mi < 4; mi++)
#pragma unroll
        for (int ni = 0; ni < 4; ni++)
#pragma unroll
            for (int q = 0; q < 4; q++) acc[mi][ni][q] = 0.f;

    auto load_stage = [&](int stage, int kc) {
        const uint32_t sb = sbase + stage * STAGE_BYTES;
        const int kofs = kc * 32 + lk;
#pragma unroll
        for (int it = 0; it < 2; it++) {
            int r = lr + it * 64;
            uint32_t so = (uint32_t)(r * SROW + lk) * 2;
            int ar = row0 + r;
            bool ok = ar < Nn;
            int arc = ok ? ar : 0;
            cp16(sb + OFF_AHI + so, Ahi + (size_t)arc * K + kofs, ok);
            cp16(sb + OFF_ALO + so, Alo + (size_t)arc * K + kofs, ok);
            cp16(sb + OFF_BHI + so, Bhi + (size_t)(n0 + r) * K + kofs, true);
            cp16(sb + OFF_BLO + so, Blo + (size_t)(n0 + r) * K + kofs, true);
        }
        asm volatile("cp.async.commit_group;" ::: "memory");
    };

    load_stage(0, 0);

    for (int kc = 0; kc < KC; kc++) {
        const int stage = kc & 1;
        if (kc + 1 < KC) {
            load_stage((kc + 1) & 1, kc + 1);
            asm volatile("cp.async.wait_group 1;" ::: "memory");
        } else {
            asm volatile("cp.async.wait_group 0;" ::: "memory");
        }
        __syncthreads();

        const uint32_t sb = sbase + stage * STAGE_BYTES;

#pragma unroll
        for (int ks = 0; ks < 2; ks++) {
            const uint32_t kbB = (uint32_t)(ks * 16 * 2);
            uint32_t a_f[4][4], bh[8], bl[8];
#pragma unroll
            for (int p = 0; p < 2; p++) {
                ldsm4(bh + p * 4, sb + OFF_BHI + b_base + p * (16 * SROW * 2) + kbB);
                ldsm4(bl + p * 4, sb + OFF_BLO + b_base + p * (16 * SROW * 2) + kbB);
            }
#pragma unroll
            for (int mi = 0; mi < 4; mi++)
                ldsm4(a_f[mi], sb + OFF_AHI + a_base + mi * (16 * SROW * 2) + kbB);
#pragma unroll
            for (int mi = 0; mi < 4; mi++)
#pragma unroll
                for (int ni = 0; ni < 4; ni++) {
                    mma16816(acc[mi][ni], a_f[mi], bh + ni * 2);
                    mma16816(acc[mi][ni], a_f[mi], bl + ni * 2);
                }
#pragma unroll
            for (int mi = 0; mi < 4; mi++)
                ldsm4(a_f[mi], sb + OFF_ALO + a_base + mi * (16 * SROW * 2) + kbB);
#pragma unroll
            for (int mi = 0; mi < 4; mi++)
#pragma unroll
                for (int ni = 0; ni < 4; ni++)
                    mma16816(acc[mi][ni], a_f[mi], bh + ni * 2);
        }
        __syncthreads();
    }

    const bool isR = (n0 >= Dhalf);
    const int cbase = (isR ? (n0 - Dhalf) : n0) + wc * 32;
#pragma unroll
    for (int mi = 0; mi < 4; mi++) {
        int r1 = row0 + wr * 64 + mi * 16 + tr;
        int r2 = r1 + 8;
#pragma unroll
        for (int ni = 0; ni < 4; ni++) {
            int cc = cbase + ni * 8 + tc;
            if (isR) {
                float bx = pb[cc], by = pb[cc + 1];
                if (r1 < Nn) {
                    float2 o = make_float2(acc[mi][ni][0] + bx, acc[mi][ni][1] + by);
                    *reinterpret_cast<float2*>(Rout + (size_t)r1 * Dhalf + cc) = o;
                }
                if (r2 < Nn) {
                    float2 o = make_float2(acc[mi][ni][2] + bx, acc[mi][ni][3] + by);
                    *reinterpret_cast<float2*>(Rout + (size_t)r2 * Dhalf + cc) = o;
                }
            } else {
                if (r1 < Nn)
                    *reinterpret_cast<__half2*>(Hout + (size_t)r1 * Dhalf + cc) =
                        __floats2half2_rn(acc[mi][ni][0], acc[mi][ni][1]);
                if (r2 < Nn)
                    *reinterpret_cast<__half2*>(Hout + (size_t)r2 * Dhalf + cc) =
                        __floats2half2_rn(acc[mi][ni][2], acc[mi][ni][3]);
            }
        }
    }

    // ---- fused attention scores (from fp32 accumulators) ----
    if (Hh != 0 && !isR) {
        const float* as_sl = asv + n0 + wc * 32;
        const float* ad_sl = adv + n0 + wc * 32;
        float as_c[8], ad_c[8];
#pragma unroll
        for (int ni = 0; ni < 4; ni++) {
            int c0 = ni * 8 + tc;
            as_c[ni * 2]     = as_sl[c0];
            as_c[ni * 2 + 1] = as_sl[c0 + 1];
            ad_c[ni * 2]     = ad_sl[c0];
            ad_c[ni * 2 + 1] = ad_sl[c0 + 1];
        }
        float* sAS = reinterpret_cast<float*>(smem);
        float* sAD = reinterpret_cast<float*>(smem) + 128;
        if (Hh < 0) {
            if (tid < 128) { sAS[tid] = 0.f; sAD[tid] = 0.f; }
            __syncthreads();
        }
#pragma unroll
        for (int mi = 0; mi < 4; mi++) {
            int lrow1 = wr * 64 + mi * 16 + tr;
            int lrow2 = lrow1 + 8;
            float as1 = 0.f, ad1 = 0.f, as2 = 0.f, ad2 = 0.f;
#pragma unroll
            for (int ni = 0; ni < 4; ni++) {
                as1 = fmaf(acc[mi][ni][0], as_c[ni * 2], fmaf(acc[mi][ni][1], as_c[ni * 2 + 1], as1));
                ad1 = fmaf(acc[mi][ni][0], ad_c[ni * 2], fmaf(acc[mi][ni][1], ad_c[ni * 2 + 1], ad1));
                as2 = fmaf(acc[mi][ni][2], as_c[ni * 2], fmaf(acc[mi][ni][3], as_c[ni * 2 + 1], as2));
                ad2 = fmaf(acc[mi][ni][2], ad_c[ni * 2], fmaf(acc[mi][ni][3], ad_c[ni * 2 + 1], ad2));
            }
#pragma unroll
            for (int o = 1; o < 4; o <<= 1) {
                as1 += __shfl_xor_sync(0xFFFFFFFFu, as1, o);
                ad1 += __shfl_xor_sync(0xFFFFFFFFu, ad1, o);
                as2 += __shfl_xor_sync(0xFFFFFFFFu, as2, o);
                ad2 += __shfl_xor_sync(0xFFFFFFFFu, ad2, o);
            }
            if ((lane & 3) == 0) {
                if (Hh > 0) {
                    const int head = (n0 >> 5) + wc;
                    int r1 = row0 + lrow1, r2 = row0 + lrow2;
                    if (r1 < Nn) { g_asrc[r1 * Hh + head] = as1; g_adst[r1 * Hh + head] = ad1; }
                    if (r2 < Nn) { g_asrc[r2 * Hh + head] = as2; g_adst[r2 * Hh + head] = ad2; }
                } else {
                    atomicAdd(&sAS[lrow1], as1); atomicAdd(&sAD[lrow1], ad1);
                    atomicAdd(&sAS[lrow2], as2); atomicAdd(&sAD[lrow2], ad2);
                }
            }
        }
        if (Hh < 0) {
            __syncthreads();
            if (tid < 128 && row0 + tid < Nn) {
                g_asrc[row0 + tid] = sAS[tid];
                g_adst[row0 + tid] = sAD[tid];
            }
        }
    }
}

// ============ fused GAT gather (fp16 H) + softmax + bias + LN + residual + ELU ============
// FPL = D/32 features per lane (8 for D=256, 4 for D=128).
template<int Hh, int C, bool WB16, bool POOL>
__global__ __launch_bounds__(256) void k_gat(
        const __half* __restrict__ H, const float* __restrict__ R,
        const float* __restrict__ bias, const float* __restrict__ gam,
        const float* __restrict__ bet,
        __nv_bfloat16* __restrict__ Ohi, __nv_bfloat16* __restrict__ Olo,
        const int* __restrict__ batch, float* __restrict__ out) {
    constexpr int D = Hh * C;
    constexpr int FPL = D / 32;           // 8 or 4

    int n = blockIdx.x * (blockDim.x >> 5) + (threadIdx.x >> 5);
    if (n >= Nn) return;
    int lane = threadIdx.x & 31;
    const int j0 = lane * FPL;            // this lane's feature base
    const int head = j0 / C;

    float adst_l = (lane < Hh) ? g_adst[n * Hh + lane] : 0.f;
    float denom_l = 0.f;
    float acc[FPL];
#pragma unroll
    for (int q = 0; q < FPL; q++) acc[q] = 0.f;

    int beg = g_off[n];
    int deg = g_deg[n];
    int s_next = (deg > 0) ? g_srcs[beg] : n;

    for (int e = 0; e <= deg; e++) {
        int s = s_next;
        s_next = (e + 1 < deg) ? g_srcs[beg + e + 1] : n;
        float w_l = 0.f;
        if (lane < Hh) {
            float ev = lrelu(g_asrc[s * Hh + lane] + adst_l);
            w_l = __expf(ev);
            denom_l += w_l;
        }
        float wj = __shfl_sync(0xFFFFFFFFu, w_l, head);
        const __half* hp = H + (size_t)s * D + j0;
        if (FPL == 8) {
            uint4 hv = *reinterpret_cast<const uint4*>(hp);
            float2 q0 = __half22float2(*reinterpret_cast<__half2*>(&hv.x));
            float2 q1 = __half22float2(*reinterpret_cast<__half2*>(&hv.y));
            float2 q2 = __half22float2(*reinterpret_cast<__half2*>(&hv.z));
            float2 q3 = __half22float2(*reinterpret_cast<__half2*>(&hv.w));
            acc[0] = fmaf(wj, q0.x, acc[0]); acc[1] = fmaf(wj, q0.y, acc[1]);
            acc[2] = fmaf(wj, q1.x, acc[2]); acc[3] = fmaf(wj, q1.y, acc[3]);
            acc[4] = fmaf(wj, q2.x, acc[4]); acc[5] = fmaf(wj, q2.y, acc[5]);
            acc[6] = fmaf(wj, q3.x, acc[6]); acc[7] = fmaf(wj, q3.y, acc[7]);
        } else {
            uint2 hv = *reinterpret_cast<const uint2*>(hp);
            float2 q0 = __half22float2(*reinterpret_cast<__half2*>(&hv.x));
            float2 q1 = __half22float2(*reinterpret_cast<__half2*>(&hv.y));
            acc[0] = fmaf(wj, q0.x, acc[0]); acc[1] = fmaf(wj, q0.y, acc[1]);
            acc[2] = fmaf(wj, q1.x, acc[2]); acc[3] = fmaf(wj, q1.y, acc[3]);
        }
    }

    float dj = __shfl_sync(0xFFFFFFFFu, denom_l, head) + 1e-16f;
    float inv = 1.0f / dj;

    float vals[FPL];
    float s1 = 0.f, s2 = 0.f;
#pragma unroll
    for (int q = 0; q < FPL; q++) {
        float v = fmaf(acc[q], inv, bias[j0 + q]);
        vals[q] = v;
        s1 += v;
        s2 = fmaf(v, v, s2);
    }
#pragma unroll
    for (int o = 16; o > 0; o >>= 1) {
        s1 += __shfl_xor_sync(0xFFFFFFFFu, s1, o);
        s2 += __shfl_xor_sync(0xFFFFFFFFu, s2, o);
    }
    float mean = s1 / (float)D;
    float var = s2 / (float)D - mean * mean;
    float rinv = rsqrtf(var + 1e-5f);

    float o_[FPL];
#pragma unroll
    for (int q = 0; q < FPL; q++) {
        float xv = (vals[q] - mean) * rinv * gam[j0 + q] + bet[j0 + q] + R[(size_t)n * D + j0 + q];
        o_[q] = xv > 0.f ? xv : expm1f(xv);
    }

    if (WB16) {
        __nv_bfloat16 hh[FPL], ll[FPL];
#pragma unroll
        for (int q = 0; q < FPL; q++) {
            hh[q] = __float2bfloat16(o_[q]);
            ll[q] = __float2bfloat16(o_[q] - __bfloat162float(hh[q]));
        }
        __nv_bfloat162* OH = reinterpret_cast<__nv_bfloat162*>(Ohi + (size_t)n * D + j0);
        __nv_bfloat162* OL = reinterpret_cast<__nv_bfloat162*>(Olo + (size_t)n * D + j0);
#pragma unroll
        for (int q = 0; q < FPL / 2; q++) {
            OH[q] = __nv_bfloat162(hh[2 * q], hh[2 * q + 1]);
            OL[q] = __nv_bfloat162(ll[2 * q], ll[2 * q + 1]);
        }
    } else if (POOL) {
        int b = batch[n];
        red4(&out[b * 128 + j0], make_float4(o_[0], o_[1], o_[2], o_[3]));
        if (lane == 0) atomicAdd(&g_cnt[b], 1.0f);
    }
}

// =========================== pooling finalize ===========================
__global__ void k_pool_zero(float* __restrict__ out) {
    int idx = blockIdx.x * blockDim.x + threadIdx.x;
    if (idx < Gg * 128) out[idx] = 0.f;
    if (idx < Gg) g_cnt[idx] = 0.f;
}
__global__ void k_pool_div(float* __restrict__ out) {
    int idx = blockIdx.x * blockDim.x + threadIdx.x;
    if (idx >= Gg * 128) return;
    out[idx] /= fmaxf(g_cnt[idx >> 7], 1.0f);
}

// =========================== host ===========================
extern "C" void kernel_launch(void* const* d_in, const int* in_sizes, int n_in,
                              void* d_out, int out_size) {
    const float* x   = (const float*)d_in[0];
    const int* ei    = (const int*)d_in[1];
    const int* batch = (const int*)d_in[2];
    const float* W1 = (const float*)d_in[3],  *as1 = (const float*)d_in[4],
               *ad1 = (const float*)d_in[5],  *b1  = (const float*)d_in[6],
               *g1  = (const float*)d_in[7],  *be1 = (const float*)d_in[8],
               *pw1 = (const float*)d_in[9],  *pb1 = (const float*)d_in[10];
    const float* W2 = (const float*)d_in[11], *as2 = (const float*)d_in[12],
               *ad2 = (const float*)d_in[13], *b2  = (const float*)d_in[14],
               *g2  = (const float*)d_in[15], *be2 = (const float*)d_in[16],
               *pw2 = (const float*)d_in[17], *pb2 = (const float*)d_in[18];
    const float* W3 = (const float*)d_in[19], *as3 = (const float*)d_in[20],
               *ad3 = (const float*)d_in[21], *b3  = (const float*)d_in[22],
               *g3  = (const float*)d_in[23], *be3 = (const float*)d_in[24],
               *pw3 = (const float*)d_in[25], *pb3 = (const float*)d_in[26];
    float* out = (float*)d_out;

    void *pH_, *pR_, *pAhi_, *pAlo_, *pBhi_, *pBlo_;
    cudaGetSymbolAddress(&pH_,  g_H);
    cudaGetSymbolAddress(&pR_,  g_R);
    cudaGetSymbolAddress(&pAhi_, g_Ahi);
    cudaGetSymbolAddress(&pAlo_, g_Alo);
    cudaGetSymbolAddress(&pBhi_, g_Bhi);
    cudaGetSymbolAddress(&pBlo_, g_Blo);
    __half* pH = (__half*)pH_;
    float* pR  = (float*)pR_;
    __nv_bfloat16* pAhi = (__nv_bfloat16*)pAhi_;
    __nv_bfloat16* pAlo = (__nv_bfloat16*)pAlo_;
    __nv_bfloat16* pBhi = (__nv_bfloat16*)pBhi_;
    __nv_bfloat16* pBlo = (__nv_bfloat16*)pBlo_;

    cudaFuncSetAttribute(k_hgemm, cudaFuncAttributeMaxDynamicSharedMemorySize, 2 * STAGE_BYTES);

    static cudaStream_t s2 = nullptr;
    static cudaEvent_t evFork = nullptr, evSide = nullptr;
    if (!s2) {
        cudaStreamCreateWithFlags(&s2, cudaStreamNonBlocking);
        cudaEventCreateWithFlags(&evFork, cudaEventDisableTiming);
        cudaEventCreateWithFlags(&evSide, cudaEventDisableTiming);
    }

    const int TB = 256;
    const int MT = (Nn + 127) / 128;

    // ---- fork: side stream does CSR build + prepack L2/L3 + pool zero ----
    cudaEventRecord(evFork, 0);
    cudaStreamWaitEvent(s2, evFork, 0);

    k_zero_deg<<<(Nn + TB - 1) / TB, TB, 0, s2>>>();
    k_hist<<<(Ee + TB - 1) / TB, TB, 0, s2>>>(ei);
    k_scan1<<<NSCAN_BLK, 256, 0, s2>>>();
    k_scan2<<<1, 256, 0, s2>>>();
    k_scan3<<<(Nn + TB - 1) / TB, TB, 0, s2>>>();
    k_scatter<<<(Ee + TB - 1) / TB, TB, 0, s2>>>(ei);
    k_prepack<<<(2 * 128 * 256 + TB - 1) / TB, TB, 0, s2>>>(W2, pw2, 256, 128, BOFF2);
    k_prepack<<<(2 * 128 * 128 + TB - 1) / TB, TB, 0, s2>>>(W3, pw3, 128, 128, BOFF3);
    k_pool_zero<<<(Gg * 128 + TB - 1) / TB, TB, 0, s2>>>(out);
    cudaEventRecord(evSide, s2);

    // ---- main stream: layer 1 (cvt + prepack1 fused; scores fused into GEMM) ----
    k_cvt_pre<<<(CVT4_L1 + 512 * 128 + TB - 1) / TB, TB>>>(x, pAhi, pAlo, W1, pw1);
    k_hgemm<<<dim3(4, MT), 256, 2 * STAGE_BYTES>>>(pAhi, pAlo, pBhi + BOFF1, pBlo + BOFF1,
                                                   pb1, pH, pR, as1, ad1, 128, 256, 8);

    cudaStreamWaitEvent(0, evSide, 0);

    k_gat<8, 32, true, false><<<(Nn * 32 + TB - 1) / TB, TB>>>(pH, pR, b1, g1, be1,
                                                               pAhi, pAlo, nullptr, nullptr);

    // ---- Layer 2 (scores fused) ----
    k_hgemm<<<dim3(2, MT), 256, 2 * STAGE_BYTES>>>(pAhi, pAlo, pBhi + BOFF2, pBlo + BOFF2,
                                                   pb2, pH, pR, as2, ad2, 256, 128, 4);
    k_gat<4, 32, true, false><<<(Nn * 32 + TB - 1) / TB, TB>>>(pH, pR, b2, g2, be2,
                                                               pAhi, pAlo, nullptr, nullptr);

    // ---- Layer 3 (scores fused via smem reduce; pool fused into gat) ----
    k_hgemm<<<dim3(2, MT), 256, 2 * STAGE_BYTES>>>(pAhi, pAlo, pBhi + BOFF3, pBlo + BOFF3,
                                                   pb3, pH, pR, as3, ad3, 128, 128, -1);
    k_gat<1, 128, false, true><<<(Nn * 32 + TB - 1) / TB, TB>>>(pH, pR, b3, g3, be3,
                                                                nullptr, nullptr, batch, out);

    k_pool_div<<<(Gg * 128 + TB - 1) / TB, TB>>>(out);
}

// round 10
// speedup vs baseline: 1.2096x; 1.0915x over previous
#include <cuda_runtime.h>
#include <cuda_bf16.h>
#include <cuda_fp16.h>
#include <math.h>
#include <stdint.h>

#define Nn 50000
#define Ee 800000
#define Gg 512
#define NSCAN_BLK 196          // ceil(50000/256)

// weight pack region offsets (elements)
#define BOFF1 0          // L1: 512 x 128
#define BOFF2 65536      // L2: 256 x 256
#define BOFF3 131072     // L3: 256 x 128
#define BTOT  163840

// ---------------- scratch ----------------
__device__ __align__(256) __half g_H[Nn * 256];    // GAT features, fp16
__device__ __align__(256) float g_R[Nn * 256];
__device__ __align__(256) float g_asrc[Nn * 8];
__device__ __align__(256) float g_adst[Nn * 8];
__device__ __align__(256) float g_cnt[Gg];
// fp16 hi/lo split activations (exact to ~2^-23) + single-fp16 weights
__device__ __align__(256) __half g_Ahi[Nn * 256];
__device__ __align__(256) __half g_Alo[Nn * 256];
__device__ __align__(256) __half g_B[BTOT];
// CSR
__device__ int g_deg[Nn];
__device__ int g_off[Nn];
__device__ int g_cur[Nn];
__device__ int g_srcs[Ee];
__device__ int g_bsum[256];

__device__ __forceinline__ float lrelu(float x) { return x > 0.0f ? x : 0.2f * x; }
__device__ __forceinline__ void red4(float* p, float4 v) {
    atomicAdd(reinterpret_cast<float4*>(p), v);
}

// =========================== CSR build ===========================
__global__ void k_zero_deg() {
    int i = blockIdx.x * blockDim.x + threadIdx.x;
    if (i < Nn) g_deg[i] = 0;
}
__global__ void k_hist(const int* __restrict__ ei) {
    int e = blockIdx.x * blockDim.x + threadIdx.x;
    if (e < Ee) atomicAdd(&g_deg[ei[Ee + e]], 1);
}
__global__ void k_scan1() {
    __shared__ int sh[256];
    int tid = threadIdx.x;
    int i = blockIdx.x * 256 + tid;
    int v = (i < Nn) ? g_deg[i] : 0;
    sh[tid] = v; __syncthreads();
    for (int off = 1; off < 256; off <<= 1) {
        int t = (tid >= off) ? sh[tid - off] : 0;
        __syncthreads();
        sh[tid] += t;
        __syncthreads();
    }
    if (i < Nn) g_off[i] = sh[tid] - v;
    if (tid == 255) g_bsum[blockIdx.x] = sh[255];
}
__global__ void k_scan2() {
    __shared__ int sh[256];
    int tid = threadIdx.x;
    int v = (tid < NSCAN_BLK) ? g_bsum[tid] : 0;
    sh[tid] = v; __syncthreads();
    for (int off = 1; off < 256; off <<= 1) {
        int t = (tid >= off) ? sh[tid - off] : 0;
        __syncthreads();
        sh[tid] += t;
        __syncthreads();
    }
    if (tid < NSCAN_BLK) g_bsum[tid] = sh[tid] - v;
}
__global__ void k_scan3() {
    int i = blockIdx.x * blockDim.x + threadIdx.x;
    if (i < Nn) {
        g_off[i] += g_bsum[i >> 8];
        g_cur[i] = 0;
    }
}
__global__ void k_scatter(const int* __restrict__ ei) {
    int e = blockIdx.x * blockDim.x + threadIdx.x;
    if (e >= Ee) return;
    int d = ei[Ee + e];
    int pos = g_off[d] + atomicAdd(&g_cur[d], 1);
    g_srcs[pos] = ei[e];
}

// =========== fused: fp32->fp16 hi/lo split of x  +  prepack of layer-1 weights ===========
#define CVT4_L1 (Nn * 128 / 4)
__global__ void k_cvt_pre(const float* __restrict__ X,
                          __half* __restrict__ hi, __half* __restrict__ lo,
                          const float* __restrict__ W, const float* __restrict__ pw) {
    int idx = blockIdx.x * blockDim.x + threadIdx.x;
    if (idx < CVT4_L1) {
        float4 v = reinterpret_cast<const float4*>(X)[idx];
        __half h0 = __float2half_rn(v.x), h1 = __float2half_rn(v.y);
        __half h2 = __float2half_rn(v.z), h3 = __float2half_rn(v.w);
        __half l0 = __float2half_rn(v.x - __half2float(h0));
        __half l1 = __float2half_rn(v.y - __half2float(h1));
        __half l2 = __float2half_rn(v.z - __half2float(h2));
        __half l3 = __float2half_rn(v.w - __half2float(h3));
        __half2* H2 = reinterpret_cast<__half2*>(hi);
        __half2* L2 = reinterpret_cast<__half2*>(lo);
        H2[idx * 2]     = __halves2half2(h0, h1);
        H2[idx * 2 + 1] = __halves2half2(h2, h3);
        L2[idx * 2]     = __halves2half2(l0, l1);
        L2[idx * 2 + 1] = __halves2half2(l2, l3);
    } else {
        int j = idx - CVT4_L1;                 // 0 .. 512*128-1
        if (j < 512 * 128) {
            const int K = 128, Dhalf = 256;
            int n = j / K, k = j - n * K;
            float w = (n < Dhalf) ? W[(size_t)k * Dhalf + n]
                                  : pw[(size_t)k * Dhalf + (n - Dhalf)];
            g_B[BOFF1 + j] = __float2half_rn(w);
        }
    }
}

// prepack (layers 2/3, on side stream)
__global__ void k_prepack(const float* __restrict__ W, const float* __restrict__ pw,
                          int K, int Dhalf, int boff) {
    int idx = blockIdx.x * blockDim.x + threadIdx.x;
    int Ncat = 2 * Dhalf;
    if (idx >= Ncat * K) return;
    int n = idx / K, k = idx - n * K;
    float w = (n < Dhalf) ? W[(size_t)k * Dhalf + n] : pw[(size_t)k * Dhalf + (n - Dhalf)];
    g_B[boff + idx] = __float2half_rn(w);
}

// =========================== HMMA GEMM (fp16 2-pass, cp.async + ldmatrix) ===========================
#define SROW 40
#define STAGE_BYTES 30720
#define OFF_AHI 0
#define OFF_ALO 10240
#define OFF_B   20480

__device__ __forceinline__ void mma16816(float* d, const uint32_t* a, const uint32_t* b) {
    asm volatile(
        "mma.sync.aligned.m16n8k16.row.col.f32.f16.f16.f32 "
        "{%0,%1,%2,%3}, {%4,%5,%6,%7}, {%8,%9}, {%0,%1,%2,%3};"
        : "+f"(d[0]), "+f"(d[1]), "+f"(d[2]), "+f"(d[3])
        : "r"(a[0]), "r"(a[1]), "r"(a[2]), "r"(a[3]), "r"(b[0]), "r"(b[1]));
}

__device__ __forceinline__ void ldsm4(uint32_t* r, uint32_t addr) {
    asm volatile("ldmatrix.sync.aligned.m8n8.x4.shared.b16 {%0,%1,%2,%3}, [%4];"
                 : "=r"(r[0]), "=r"(r[1]), "=r"(r[2]), "=r"(r[3]) : "r"(addr));
}

__device__ __forceinline__ uint32_t smem_u32(const void* p) {
    uint32_t a;
    asm("{ .reg .u64 t; cvta.to.shared.u64 t, %1; cvt.u32.u64 %0, t; }" : "=r"(a) : "l"(p));
    return a;
}

__device__ __forceinline__ void cp16(uint32_t dst, const void* src, bool ok) {
    asm volatile(
        "{\n\t.reg .pred p;\n\tsetp.ne.u32 p, %2, 0;\n\t"
        "@p cp.async.cg.shared.global [%0], [%1], 16;\n\t"
        "@!p cp.async.cg.shared.global [%0], [%1], 16, 0;\n\t}"
        :: "r"(dst), "l"(src), "r"((unsigned)ok) : "memory");
}

// Hh > 0 : C=32 fused per-head scores; Hh == -1: layer-3 scores via smem reduce
__global__ __launch_bounds__(256) void k_hgemm(
        const __half* __restrict__ Ahi, const __half* __restrict__ Alo,
        const __half* __restrict__ B,
        const float* __restrict__ pb, __half* __restrict__ Hout, float* __restrict__ Rout,
        const float* __restrict__ asv, const float* __restrict__ adv,
        int K, int Dhalf, int Hh) {
    extern __shared__ __align__(16) char smem[];
    const uint32_t sbase = smem_u32(smem);

    const int tid = threadIdx.x;
    const int wid = tid >> 5, lane = tid & 31;
    const int row0 = blockIdx.y * 128;
    const int n0 = blockIdx.x * 128;
    const int KC = K >> 5;
    const int wr = wid >> 2;
    const int wc = wid & 3;
    const int tr = lane >> 2;
    const int tc = (lane & 3) * 2;

    const int lr = tid >> 2;
    const int lk = (tid & 3) * 8;

    const uint32_t a_base = (uint32_t)(((wr * 64 + (lane & 15)) * SROW + (lane >> 4) * 8) * 2);
    const int bt = lane >> 3;
    const uint32_t b_base = (uint32_t)((((wc * 32 + (bt >> 1) * 8 + (lane & 7))) * SROW + (bt & 1) * 8) * 2);

    float acc[4][4][4];
#pragma unroll
    for (int mi = 0; mi < 4; mi++)
#pragma unroll
        for (int ni = 0; ni < 4; ni++)
#pragma unroll
            for (int q = 0; q < 4; q++) acc[mi][ni][q] = 0.f;

    auto load_stage = [&](int stage, int kc) {
        const uint32_t sb = sbase + stage * STAGE_BYTES;
        const int kofs = kc * 32 + lk;
#pragma unroll
        for (int it = 0; it < 2; it++) {
            int r = lr + it * 64;
            uint32_t so = (uint32_t)(r * SROW + lk) * 2;
            int ar = row0 + r;
            bool ok = ar < Nn;
            int arc = ok ? ar : 0;
            cp16(sb + OFF_AHI + so, Ahi + (size_t)arc * K + kofs, ok);
            cp16(sb + OFF_ALO + so, Alo + (size_t)arc * K + kofs, ok);
            cp16(sb + OFF_B + so, B + (size_t)(n0 + r) * K + kofs, true);
        }
        asm volatile("cp.async.commit_group;" ::: "memory");
    };

    load_stage(0, 0);

    for (int kc = 0; kc < KC; kc++) {
        const int stage = kc & 1;
        if (kc + 1 < KC) {
            load_stage((kc + 1) & 1, kc + 1);
            asm volatile("cp.async.wait_group 1;" ::: "memory");
        } else {
            asm volatile("cp.async.wait_group 0;" ::: "memory");
        }
        __syncthreads();

        const uint32_t sb = sbase + stage * STAGE_BYTES;

#pragma unroll
        for (int ks = 0; ks < 2; ks++) {
            const uint32_t kbB = (uint32_t)(ks * 16 * 2);
            uint32_t a_f[4][4], bh[8];
#pragma unroll
            for (int p = 0; p < 2; p++)
                ldsm4(bh + p * 4, sb + OFF_B + b_base + p * (16 * SROW * 2) + kbB);
#pragma unroll
            for (int mi = 0; mi < 4; mi++)
                ldsm4(a_f[mi], sb + OFF_AHI + a_base + mi * (16 * SROW * 2) + kbB);
#pragma unroll
            for (int mi = 0; mi < 4; mi++)
#pragma unroll
                for (int ni = 0; ni < 4; ni++)
                    mma16816(acc[mi][ni], a_f[mi], bh + ni * 2);
#pragma unroll
            for (int mi = 0; mi < 4; mi++)
                ldsm4(a_f[mi], sb + OFF_ALO + a_base + mi * (16 * SROW * 2) + kbB);
#pragma unroll
            for (int mi = 0; mi < 4; mi++)
#pragma unroll
                for (int ni = 0; ni < 4; ni++)
                    mma16816(acc[mi][ni], a_f[mi], bh + ni * 2);
        }
        __syncthreads();
    }

    const bool isR = (n0 >= Dhalf);
    const int cbase = (isR ? (n0 - Dhalf) : n0) + wc * 32;
#pragma unroll
    for (int mi = 0; mi < 4; mi++) {
        int r1 = row0 + wr * 64 + mi * 16 + tr;
        int r2 = r1 + 8;
#pragma unroll
        for (int ni = 0; ni < 4; ni++) {
            int cc = cbase + ni * 8 + tc;
            if (isR) {
                float bx = pb[cc], by = pb[cc + 1];
                if (r1 < Nn) {
                    float2 o = make_float2(acc[mi][ni][0] + bx, acc[mi][ni][1] + by);
                    *reinterpret_cast<float2*>(Rout + (size_t)r1 * Dhalf + cc) = o;
                }
                if (r2 < Nn) {
                    float2 o = make_float2(acc[mi][ni][2] + bx, acc[mi][ni][3] + by);
                    *reinterpret_cast<float2*>(Rout + (size_t)r2 * Dhalf + cc) = o;
                }
            } else {
                if (r1 < Nn)
                    *reinterpret_cast<__half2*>(Hout + (size_t)r1 * Dhalf + cc) =
                        __floats2half2_rn(acc[mi][ni][0], acc[mi][ni][1]);
                if (r2 < Nn)
                    *reinterpret_cast<__half2*>(Hout + (size_t)r2 * Dhalf + cc) =
                        __floats2half2_rn(acc[mi][ni][2], acc[mi][ni][3]);
            }
        }
    }

    // ---- fused attention scores (from fp32 accumulators) ----
    if (Hh != 0 && !isR) {
        const float* as_sl = asv + n0 + wc * 32;
        const float* ad_sl = adv + n0 + wc * 32;
        float as_c[8], ad_c[8];
#pragma unroll
        for (int ni = 0; ni < 4; ni++) {
            int c0 = ni * 8 + tc;
            as_c[ni * 2]     = as_sl[c0];
            as_c[ni * 2 + 1] = as_sl[c0 + 1];
            ad_c[ni * 2]     = ad_sl[c0];
            ad_c[ni * 2 + 1] = ad_sl[c0 + 1];
        }
        float* sAS = reinterpret_cast<float*>(smem);
        float* sAD = reinterpret_cast<float*>(smem) + 128;
        if (Hh < 0) {
            if (tid < 128) { sAS[tid] = 0.f; sAD[tid] = 0.f; }
            __syncthreads();
        }
#pragma unroll
        for (int mi = 0; mi < 4; mi++) {
            int lrow1 = wr * 64 + mi * 16 + tr;
            int lrow2 = lrow1 + 8;
            float as1 = 0.f, ad1 = 0.f, as2 = 0.f, ad2 = 0.f;
#pragma unroll
            for (int ni = 0; ni < 4; ni++) {
                as1 = fmaf(acc[mi][ni][0], as_c[ni * 2], fmaf(acc[mi][ni][1], as_c[ni * 2 + 1], as1));
                ad1 = fmaf(acc[mi][ni][0], ad_c[ni * 2], fmaf(acc[mi][ni][1], ad_c[ni * 2 + 1], ad1));
                as2 = fmaf(acc[mi][ni][2], as_c[ni * 2], fmaf(acc[mi][ni][3], as_c[ni * 2 + 1], as2));
                ad2 = fmaf(acc[mi][ni][2], ad_c[ni * 2], fmaf(acc[mi][ni][3], ad_c[ni * 2 + 1], ad2));
            }
#pragma unroll
            for (int o = 1; o < 4; o <<= 1) {
                as1 += __shfl_xor_sync(0xFFFFFFFFu, as1, o);
                ad1 += __shfl_xor_sync(0xFFFFFFFFu, ad1, o);
                as2 += __shfl_xor_sync(0xFFFFFFFFu, as2, o);
                ad2 += __shfl_xor_sync(0xFFFFFFFFu, ad2, o);
            }
            if ((lane & 3) == 0) {
                if (Hh > 0) {
                    const int head = (n0 >> 5) + wc;
                    int r1 = row0 + lrow1, r2 = row0 + lrow2;
                    if (r1 < Nn) { g_asrc[r1 * Hh + head] = as1; g_adst[r1 * Hh + head] = ad1; }
                    if (r2 < Nn) { g_asrc[r2 * Hh + head] = as2; g_adst[r2 * Hh + head] = ad2; }
                } else {
                    atomicAdd(&sAS[lrow1], as1); atomicAdd(&sAD[lrow1], ad1);
                    atomicAdd(&sAS[lrow2], as2); atomicAdd(&sAD[lrow2], ad2);
                }
            }
        }
        if (Hh < 0) {
            __syncthreads();
            if (tid < 128 && row0 + tid < Nn) {
                g_asrc[row0 + tid] = sAS[tid];
                g_adst[row0 + tid] = sAD[tid];
            }
        }
    }
}

// ============ fused GAT gather (fp16 H) + softmax + bias + LN + residual + ELU ============
template<int Hh, int C, bool WB16, bool POOL>
__global__ __launch_bounds__(256) void k_gat(
        const __half* __restrict__ H, const float* __restrict__ R,
        const float* __restrict__ bias, const float* __restrict__ gam,
        const float* __restrict__ bet,
        __half* __restrict__ Ohi, __half* __restrict__ Olo,
        const int* __restrict__ batch, float* __restrict__ out) {
    constexpr int D = Hh * C;
    constexpr int FPL = D / 32;           // 8 or 4

    int n = blockIdx.x * (blockDim.x >> 5) + (threadIdx.x >> 5);
    if (n >= Nn) return;
    int lane = threadIdx.x & 31;
    const int j0 = lane * FPL;
    const int head = j0 / C;

    float adst_l = (lane < Hh) ? g_adst[n * Hh + lane] : 0.f;
    float denom_l = 0.f;
    float acc[FPL];
#pragma unroll
    for (int q = 0; q < FPL; q++) acc[q] = 0.f;

    int beg = g_off[n];
    int deg = g_deg[n];
    int s_next = (deg > 0) ? g_srcs[beg] : n;

    for (int e = 0; e <= deg; e++) {
        int s = s_next;
        s_next = (e + 1 < deg) ? g_srcs[beg + e + 1] : n;
        float w_l = 0.f;
        if (lane < Hh) {
            float ev = lrelu(g_asrc[s * Hh + lane] + adst_l);
            w_l = __expf(ev);
            denom_l += w_l;
        }
        float wj = __shfl_sync(0xFFFFFFFFu, w_l, head);
        const __half* hp = H + (size_t)s * D + j0;
        if (FPL == 8) {
            uint4 hv = *reinterpret_cast<const uint4*>(hp);
            float2 q0 = __half22float2(*reinterpret_cast<__half2*>(&hv.x));
            float2 q1 = __half22float2(*reinterpret_cast<__half2*>(&hv.y));
            float2 q2 = __half22float2(*reinterpret_cast<__half2*>(&hv.z));
            float2 q3 = __half22float2(*reinterpret_cast<__half2*>(&hv.w));
            acc[0] = fmaf(wj, q0.x, acc[0]); acc[1] = fmaf(wj, q0.y, acc[1]);
            acc[2] = fmaf(wj, q1.x, acc[2]); acc[3] = fmaf(wj, q1.y, acc[3]);
            acc[4] = fmaf(wj, q2.x, acc[4]); acc[5] = fmaf(wj, q2.y, acc[5]);
            acc[6] = fmaf(wj, q3.x, acc[6]); acc[7] = fmaf(wj, q3.y, acc[7]);
        } else {
            uint2 hv = *reinterpret_cast<const uint2*>(hp);
            float2 q0 = __half22float2(*reinterpret_cast<__half2*>(&hv.x));
            float2 q1 = __half22float2(*reinterpret_cast<__half2*>(&hv.y));
            acc[0] = fmaf(wj, q0.x, acc[0]); acc[1] = fmaf(wj, q0.y, acc[1]);
            acc[2] = fmaf(wj, q1.x, acc[2]); acc[3] = fmaf(wj, q1.y, acc[3]);
        }
    }

    float dj = __shfl_sync(0xFFFFFFFFu, denom_l, head) + 1e-16f;
    float inv = 1.0f / dj;

    float vals[FPL];
    float s1 = 0.f, s2 = 0.f;
#pragma unroll
    for (int q = 0; q < FPL; q++) {
        float v = fmaf(acc[q], inv, bias[j0 + q]);
        vals[q] = v;
        s1 += v;
        s2 = fmaf(v, v, s2);
    }
#pragma unroll
    for (int o = 16; o > 0; o >>= 1) {
        s1 += __shfl_xor_sync(0xFFFFFFFFu, s1, o);
        s2 += __shfl_xor_sync(0xFFFFFFFFu, s2, o);
    }
    float mean = s1 / (float)D;
    float var = s2 / (float)D - mean * mean;
    float rinv = rsqrtf(var + 1e-5f);

    float o_[FPL];
#pragma unroll
    for (int q = 0; q < FPL; q++) {
        float xv = (vals[q] - mean) * rinv * gam[j0 + q] + bet[j0 + q] + R[(size_t)n * D + j0 + q];
        o_[q] = xv > 0.f ? xv : expm1f(xv);
    }

    if (WB16) {
        __half hh[FPL], ll[FPL];
#pragma unroll
        for (int q = 0; q < FPL; q++) {
            hh[q] = __float2half_rn(o_[q]);
            ll[q] = __float2half_rn(o_[q] - __half2float(hh[q]));
        }
        __half2* OH = reinterpret_cast<__half2*>(Ohi + (size_t)n * D + j0);
        __half2* OL = reinterpret_cast<__half2*>(Olo + (size_t)n * D + j0);
#pragma unroll
        for (int q = 0; q < FPL / 2; q++) {
            OH[q] = __halves2half2(hh[2 * q], hh[2 * q + 1]);
            OL[q] = __halves2half2(ll[2 * q], ll[2 * q + 1]);
        }
    } else if (POOL) {
        int b = batch[n];
        red4(&out[b * 128 + j0], make_float4(o_[0], o_[1], o_[2], o_[3]));
        if (lane == 0) atomicAdd(&g_cnt[b], 1.0f);
    }
}

// =========================== pooling finalize ===========================
__global__ void k_pool_zero(float* __restrict__ out) {
    int idx = blockIdx.x * blockDim.x + threadIdx.x;
    if (idx < Gg * 128) out[idx] = 0.f;
    if (idx < Gg) g_cnt[idx] = 0.f;
}
__global__ void k_pool_div(float* __restrict__ out) {
    int idx = blockIdx.x * blockDim.x + threadIdx.x;
    if (idx >= Gg * 128) return;
    out[idx] /= fmaxf(g_cnt[idx >> 7], 1.0f);
}

// =========================== host ===========================
extern "C" void kernel_launch(void* const* d_in, const int* in_sizes, int n_in,
                              void* d_out, int out_size) {
    const float* x   = (const float*)d_in[0];
    const int* ei    = (const int*)d_in[1];
    const int* batch = (const int*)d_in[2];
    const float* W1 = (const float*)d_in[3],  *as1 = (const float*)d_in[4],
               *ad1 = (const float*)d_in[5],  *b1  = (const float*)d_in[6],
               *g1  = (const float*)d_in[7],  *be1 = (const float*)d_in[8],
               *pw1 = (const float*)d_in[9],  *pb1 = (const float*)d_in[10];
    const float* W2 = (const float*)d_in[11], *as2 = (const float*)d_in[12],
               *ad2 = (const float*)d_in[13], *b2  = (const float*)d_in[14],
               *g2  = (const float*)d_in[15], *be2 = (const float*)d_in[16],
               *pw2 = (const float*)d_in[17], *pb2 = (const float*)d_in[18];
    const float* W3 = (const float*)d_in[19], *as3 = (const float*)d_in[20],
               *ad3 = (const float*)d_in[21], *b3  = (const float*)d_in[22],
               *g3  = (const float*)d_in[23], *be3 = (const float*)d_in[24],
               *pw3 = (const float*)d_in[25], *pb3 = (const float*)d_in[26];
    float* out = (float*)d_out;

    void *pH_, *pR_, *pAhi_, *pAlo_, *pB_;
    cudaGetSymbolAddress(&pH_,  g_H);
    cudaGetSymbolAddress(&pR_,  g_R);
    cudaGetSymbolAddress(&pAhi_, g_Ahi);
    cudaGetSymbolAddress(&pAlo_, g_Alo);
    cudaGetSymbolAddress(&pB_,  g_B);
    __half* pH = (__half*)pH_;
    float* pR  = (float*)pR_;
    __half* pAhi = (__half*)pAhi_;
    __half* pAlo = (__half*)pAlo_;
    __half* pB   = (__half*)pB_;

    cudaFuncSetAttribute(k_hgemm, cudaFuncAttributeMaxDynamicSharedMemorySize, 2 * STAGE_BYTES);

    static cudaStream_t s2 = nullptr;
    static cudaEvent_t evFork = nullptr, evSide = nullptr;
    if (!s2) {
        cudaStreamCreateWithFlags(&s2, cudaStreamNonBlocking);
        cudaEventCreateWithFlags(&evFork, cudaEventDisableTiming);
        cudaEventCreateWithFlags(&evSide, cudaEventDisableTiming);
    }

    const int TB = 256;
    const int MT = (Nn + 127) / 128;

    // ---- fork: side stream does CSR build + prepack L2/L3 + pool zero ----
    cudaEventRecord(evFork, 0);
    cudaStreamWaitEvent(s2, evFork, 0);

    k_zero_deg<<<(Nn + TB - 1) / TB, TB, 0, s2>>>();
    k_hist<<<(Ee + TB - 1) / TB, TB, 0, s2>>>(ei);
    k_scan1<<<NSCAN_BLK, 256, 0, s2>>>();
    k_scan2<<<1, 256, 0, s2>>>();
    k_scan3<<<(Nn + TB - 1) / TB, TB, 0, s2>>>();
    k_scatter<<<(Ee + TB - 1) / TB, TB, 0, s2>>>(ei);
    k_prepack<<<(2 * 128 * 256 + TB - 1) / TB, TB, 0, s2>>>(W2, pw2, 256, 128, BOFF2);
    k_prepack<<<(2 * 128 * 128 + TB - 1) / TB, TB, 0, s2>>>(W3, pw3, 128, 128, BOFF3);
    k_pool_zero<<<(Gg * 128 + TB - 1) / TB, TB, 0, s2>>>(out);
    cudaEventRecord(evSide, s2);

    // ---- main stream: layer 1 ----
    k_cvt_pre<<<(CVT4_L1 + 512 * 128 + TB - 1) / TB, TB>>>(x, pAhi, pAlo, W1, pw1);
    k_hgemm<<<dim3(4, MT), 256, 2 * STAGE_BYTES>>>(pAhi, pAlo, pB + BOFF1,
                                                   pb1, pH, pR, as1, ad1, 128, 256, 8);

    cudaStreamWaitEvent(0, evSide, 0);

    k_gat<8, 32, true, false><<<(Nn * 32 + TB - 1) / TB, TB>>>(pH, pR, b1, g1, be1,
                                                               pAhi, pAlo, nullptr, nullptr);

    // ---- Layer 2 ----
    k_hgemm<<<dim3(2, MT), 256, 2 * STAGE_BYTES>>>(pAhi, pAlo, pB + BOFF2,
                                                   pb2, pH, pR, as2, ad2, 256, 128, 4);
    k_gat<4, 32, true, false><<<(Nn * 32 + TB - 1) / TB, TB>>>(pH, pR, b2, g2, be2,
                                                               pAhi, pAlo, nullptr, nullptr);

    // ---- Layer 3 ----
    k_hgemm<<<dim3(2, MT), 256, 2 * STAGE_BYTES>>>(pAhi, pAlo, pB + BOFF3,
                                                   pb3, pH, pR, as3, ad3, 128, 128, -1);
    k_gat<1, 128, false, true><<<(Nn * 32 + TB - 1) / TB, TB>>>(pH, pR, b3, g3, be3,
                                                                nullptr, nullptr, batch, out);

    k_pool_div<<<(Gg * 128 + TB - 1) / TB, TB>>>(out);
}

// round 11
// speedup vs baseline: 1.3337x; 1.1026x over previous
#include <cuda_runtime.h>
#include <cuda_bf16.h>
#include <cuda_fp16.h>
#include <math.h>
#include <stdint.h>

#define Nn 50000
#define Ee 800000
#define Gg 512
#define NSCAN_BLK 196          // ceil(50000/256)

// weight pack region offsets (elements)
#define BOFF1 0          // L1: 512 x 128
#define BOFF2 65536      // L2: 256 x 256
#define BOFF3 131072     // L3: 256 x 128
#define BTOT  163840

// ---------------- scratch ----------------
__device__ __align__(256) __half g_H[Nn * 256];    // GAT features, fp16
__device__ __align__(256) float g_R[Nn * 256];
__device__ __align__(256) float g_asrc[Nn * 8];
__device__ __align__(256) float g_adst[Nn * 8];
__device__ __align__(256) float g_cnt[Gg];
// fp16 activations (GEMM A) + fp16 weights
__device__ __align__(256) __half g_A[Nn * 256];
__device__ __align__(256) __half g_B[BTOT];
// CSR
__device__ int g_deg[Nn];
__device__ int g_off[Nn];
__device__ int g_cur[Nn];
__device__ int g_srcs[Ee];
__device__ int g_bsum[256];

__device__ __forceinline__ float lrelu(float x) { return x > 0.0f ? x : 0.2f * x; }
__device__ __forceinline__ void red4(float* p, float4 v) {
    atomicAdd(reinterpret_cast<float4*>(p), v);
}

// =========================== CSR build ===========================
__global__ void k_zero_deg() {
    int i = blockIdx.x * blockDim.x + threadIdx.x;
    if (i < Nn) g_deg[i] = 0;
}
__global__ void k_hist(const int* __restrict__ ei) {
    int e = blockIdx.x * blockDim.x + threadIdx.x;
    if (e < Ee) atomicAdd(&g_deg[ei[Ee + e]], 1);
}
__global__ void k_scan1() {
    __shared__ int sh[256];
    int tid = threadIdx.x;
    int i = blockIdx.x * 256 + tid;
    int v = (i < Nn) ? g_deg[i] : 0;
    sh[tid] = v; __syncthreads();
    for (int off = 1; off < 256; off <<= 1) {
        int t = (tid >= off) ? sh[tid - off] : 0;
        __syncthreads();
        sh[tid] += t;
        __syncthreads();
    }
    if (i < Nn) g_off[i] = sh[tid] - v;
    if (tid == 255) g_bsum[blockIdx.x] = sh[255];
}
__global__ void k_scan2() {
    __shared__ int sh[256];
    int tid = threadIdx.x;
    int v = (tid < NSCAN_BLK) ? g_bsum[tid] : 0;
    sh[tid] = v; __syncthreads();
    for (int off = 1; off < 256; off <<= 1) {
        int t = (tid >= off) ? sh[tid - off] : 0;
        __syncthreads();
        sh[tid] += t;
        __syncthreads();
    }
    if (tid < NSCAN_BLK) g_bsum[tid] = sh[tid] - v;
}
__global__ void k_scan3() {
    int i = blockIdx.x * blockDim.x + threadIdx.x;
    if (i < Nn) {
        g_off[i] += g_bsum[i >> 8];
        g_cur[i] = 0;
    }
}
__global__ void k_scatter(const int* __restrict__ ei) {
    int e = blockIdx.x * blockDim.x + threadIdx.x;
    if (e >= Ee) return;
    int d = ei[Ee + e];
    int pos = g_off[d] + atomicAdd(&g_cur[d], 1);
    g_srcs[pos] = ei[e];
}

// =========== fused: fp32->fp16 cvt of x  +  prepack of layer-1 weights ===========
#define CVT4_L1 (Nn * 128 / 4)
__global__ void k_cvt_pre(const float* __restrict__ X, __half* __restrict__ A,
                          const float* __restrict__ W, const float* __restrict__ pw) {
    int idx = blockIdx.x * blockDim.x + threadIdx.x;
    if (idx < CVT4_L1) {
        float4 v = reinterpret_cast<const float4*>(X)[idx];
        __half2* H2 = reinterpret_cast<__half2*>(A);
        H2[idx * 2]     = __floats2half2_rn(v.x, v.y);
        H2[idx * 2 + 1] = __floats2half2_rn(v.z, v.w);
    } else {
        int j = idx - CVT4_L1;                 // 0 .. 512*128-1
        if (j < 512 * 128) {
            const int K = 128, Dhalf = 256;
            int n = j / K, k = j - n * K;
            float w = (n < Dhalf) ? W[(size_t)k * Dhalf + n]
                                  : pw[(size_t)k * Dhalf + (n - Dhalf)];
            g_B[BOFF1 + j] = __float2half_rn(w);
        }
    }
}

// prepack (layers 2/3, on side stream)
__global__ void k_prepack(const float* __restrict__ W, const float* __restrict__ pw,
                          int K, int Dhalf, int boff) {
    int idx = blockIdx.x * blockDim.x + threadIdx.x;
    int Ncat = 2 * Dhalf;
    if (idx >= Ncat * K) return;
    int n = idx / K, k = idx - n * K;
    float w = (n < Dhalf) ? W[(size_t)k * Dhalf + n] : pw[(size_t)k * Dhalf + (n - Dhalf)];
    g_B[boff + idx] = __float2half_rn(w);
}

// =========================== HMMA GEMM (fp16 single-pass, cp.async + ldmatrix) ===========================
#define SROW 40
#define STAGE_BYTES 20480
#define OFF_A 0
#define OFF_B 10240

__device__ __forceinline__ void mma16816(float* d, const uint32_t* a, const uint32_t* b) {
    asm volatile(
        "mma.sync.aligned.m16n8k16.row.col.f32.f16.f16.f32 "
        "{%0,%1,%2,%3}, {%4,%5,%6,%7}, {%8,%9}, {%0,%1,%2,%3};"
        : "+f"(d[0]), "+f"(d[1]), "+f"(d[2]), "+f"(d[3])
        : "r"(a[0]), "r"(a[1]), "r"(a[2]), "r"(a[3]), "r"(b[0]), "r"(b[1]));
}

__device__ __forceinline__ void ldsm4(uint32_t* r, uint32_t addr) {
    asm volatile("ldmatrix.sync.aligned.m8n8.x4.shared.b16 {%0,%1,%2,%3}, [%4];"
                 : "=r"(r[0]), "=r"(r[1]), "=r"(r[2]), "=r"(r[3]) : "r"(addr));
}

__device__ __forceinline__ uint32_t smem_u32(const void* p) {
    uint32_t a;
    asm("{ .reg .u64 t; cvta.to.shared.u64 t, %1; cvt.u32.u64 %0, t; }" : "=r"(a) : "l"(p));
    return a;
}

__device__ __forceinline__ void cp16(uint32_t dst, const void* src, bool ok) {
    asm volatile(
        "{\n\t.reg .pred p;\n\tsetp.ne.u32 p, %2, 0;\n\t"
        "@p cp.async.cg.shared.global [%0], [%1], 16;\n\t"
        "@!p cp.async.cg.shared.global [%0], [%1], 16, 0;\n\t}"
        :: "r"(dst), "l"(src), "r"((unsigned)ok) : "memory");
}

// Hh > 0 : C=32 fused per-head scores; Hh == -1: layer-3 scores via smem reduce
__global__ __launch_bounds__(256) void k_hgemm(
        const __half* __restrict__ A, const __half* __restrict__ B,
        const float* __restrict__ pb, __half* __restrict__ Hout, float* __restrict__ Rout,
        const float* __restrict__ asv, const float* __restrict__ adv,
        int K, int Dhalf, int Hh) {
    extern __shared__ __align__(16) char smem[];
    const uint32_t sbase = smem_u32(smem);

    const int tid = threadIdx.x;
    const int wid = tid >> 5, lane = tid & 31;
    const int row0 = blockIdx.y * 128;
    const int n0 = blockIdx.x * 128;
    const int KC = K >> 5;
    const int wr = wid >> 2;
    const int wc = wid & 3;
    const int tr = lane >> 2;
    const int tc = (lane & 3) * 2;

    const int lr = tid >> 2;
    const int lk = (tid & 3) * 8;

    const uint32_t a_base = (uint32_t)(((wr * 64 + (lane & 15)) * SROW + (lane >> 4) * 8) * 2);
    const int bt = lane >> 3;
    const uint32_t b_base = (uint32_t)((((wc * 32 + (bt >> 1) * 8 + (lane & 7))) * SROW + (bt & 1) * 8) * 2);

    float acc[4][4][4];
#pragma unroll
    for (int mi = 0; mi < 4; mi++)
#pragma unroll
        for (int ni = 0; ni < 4; ni++)
#pragma unroll
            for (int q = 0; q < 4; q++) acc[mi][ni][q] = 0.f;

    auto load_stage = [&](int stage, int kc) {
        const uint32_t sb = sbase + stage * STAGE_BYTES;
        const int kofs = kc * 32 + lk;
#pragma unroll
        for (int it = 0; it < 2; it++) {
            int r = lr + it * 64;
            uint32_t so = (uint32_t)(r * SROW + lk) * 2;
            int ar = row0 + r;
            bool ok = ar < Nn;
            int arc = ok ? ar : 0;
            cp16(sb + OFF_A + so, A + (size_t)arc * K + kofs, ok);
            cp16(sb + OFF_B + so, B + (size_t)(n0 + r) * K + kofs, true);
        }
        asm volatile("cp.async.commit_group;" ::: "memory");
    };

    load_stage(0, 0);

    for (int kc = 0; kc < KC; kc++) {
        const int stage = kc & 1;
        if (kc + 1 < KC) {
            load_stage((kc + 1) & 1, kc + 1);
            asm volatile("cp.async.wait_group 1;" ::: "memory");
        } else {
            asm volatile("cp.async.wait_group 0;" ::: "memory");
        }
        __syncthreads();

        const uint32_t sb = sbase + stage * STAGE_BYTES;

#pragma unroll
        for (int ks = 0; ks < 2; ks++) {
            const uint32_t kbB = (uint32_t)(ks * 16 * 2);
            uint32_t a_f[4][4], bh[8];
#pragma unroll
            for (int p = 0; p < 2; p++)
                ldsm4(bh + p * 4, sb + OFF_B + b_base + p * (16 * SROW * 2) + kbB);
#pragma unroll
            for (int mi = 0; mi < 4; mi++)
                ldsm4(a_f[mi], sb + OFF_A + a_base + mi * (16 * SROW * 2) + kbB);
#pragma unroll
            for (int mi = 0; mi < 4; mi++)
#pragma unroll
                for (int ni = 0; ni < 4; ni++)
                    mma16816(acc[mi][ni], a_f[mi], bh + ni * 2);
        }
        __syncthreads();
    }

    const bool isR = (n0 >= Dhalf);
    const int cbase = (isR ? (n0 - Dhalf) : n0) + wc * 32;
#pragma unroll
    for (int mi = 0; mi < 4; mi++) {
        int r1 = row0 + wr * 64 + mi * 16 + tr;
        int r2 = r1 + 8;
#pragma unroll
        for (int ni = 0; ni < 4; ni++) {
            int cc = cbase + ni * 8 + tc;
            if (isR) {
                float bx = pb[cc], by = pb[cc + 1];
                if (r1 < Nn) {
                    float2 o = make_float2(acc[mi][ni][0] + bx, acc[mi][ni][1] + by);
                    *reinterpret_cast<float2*>(Rout + (size_t)r1 * Dhalf + cc) = o;
                }
                if (r2 < Nn) {
                    float2 o = make_float2(acc[mi][ni][2] + bx, acc[mi][ni][3] + by);
                    *reinterpret_cast<float2*>(Rout + (size_t)r2 * Dhalf + cc) = o;
                }
            } else {
                if (r1 < Nn)
                    *reinterpret_cast<__half2*>(Hout + (size_t)r1 * Dhalf + cc) =
                        __floats2half2_rn(acc[mi][ni][0], acc[mi][ni][1]);
                if (r2 < Nn)
                    *reinterpret_cast<__half2*>(Hout + (size_t)r2 * Dhalf + cc) =
                        __floats2half2_rn(acc[mi][ni][2], acc[mi][ni][3]);
            }
        }
    }

    // ---- fused attention scores (from fp32 accumulators) ----
    if (Hh != 0 && !isR) {
        const float* as_sl = asv + n0 + wc * 32;
        const float* ad_sl = adv + n0 + wc * 32;
        float as_c[8], ad_c[8];
#pragma unroll
        for (int ni = 0; ni < 4; ni++) {
            int c0 = ni * 8 + tc;
            as_c[ni * 2]     = as_sl[c0];
            as_c[ni * 2 + 1] = as_sl[c0 + 1];
            ad_c[ni * 2]     = ad_sl[c0];
            ad_c[ni * 2 + 1] = ad_sl[c0 + 1];
        }
        float* sAS = reinterpret_cast<float*>(smem);
        float* sAD = reinterpret_cast<float*>(smem) + 128;
        if (Hh < 0) {
            if (tid < 128) { sAS[tid] = 0.f; sAD[tid] = 0.f; }
            __syncthreads();
        }
#pragma unroll
        for (int mi = 0; mi < 4; mi++) {
            int lrow1 = wr * 64 + mi * 16 + tr;
            int lrow2 = lrow1 + 8;
            float as1 = 0.f, ad1 = 0.f, as2 = 0.f, ad2 = 0.f;
#pragma unroll
            for (int ni = 0; ni < 4; ni++) {
                as1 = fmaf(acc[mi][ni][0], as_c[ni * 2], fmaf(acc[mi][ni][1], as_c[ni * 2 + 1], as1));
                ad1 = fmaf(acc[mi][ni][0], ad_c[ni * 2], fmaf(acc[mi][ni][1], ad_c[ni * 2 + 1], ad1));
                as2 = fmaf(acc[mi][ni][2], as_c[ni * 2], fmaf(acc[mi][ni][3], as_c[ni * 2 + 1], as2));
                ad2 = fmaf(acc[mi][ni][2], ad_c[ni * 2], fmaf(acc[mi][ni][3], ad_c[ni * 2 + 1], ad2));
            }
#pragma unroll
            for (int o = 1; o < 4; o <<= 1) {
                as1 += __shfl_xor_sync(0xFFFFFFFFu, as1, o);
                ad1 += __shfl_xor_sync(0xFFFFFFFFu, ad1, o);
                as2 += __shfl_xor_sync(0xFFFFFFFFu, as2, o);
                ad2 += __shfl_xor_sync(0xFFFFFFFFu, ad2, o);
            }
            if ((lane & 3) == 0) {
                if (Hh > 0) {
                    const int head = (n0 >> 5) + wc;
                    int r1 = row0 + lrow1, r2 = row0 + lrow2;
                    if (r1 < Nn) { g_asrc[r1 * Hh + head] = as1; g_adst[r1 * Hh + head] = ad1; }
                    if (r2 < Nn) { g_asrc[r2 * Hh + head] = as2; g_adst[r2 * Hh + head] = ad2; }
                } else {
                    atomicAdd(&sAS[lrow1], as1); atomicAdd(&sAD[lrow1], ad1);
                    atomicAdd(&sAS[lrow2], as2); atomicAdd(&sAD[lrow2], ad2);
                }
            }
        }
        if (Hh < 0) {
            __syncthreads();
            if (tid < 128 && row0 + tid < Nn) {
                g_asrc[row0 + tid] = sAS[tid];
                g_adst[row0 + tid] = sAD[tid];
            }
        }
    }
}

// ============ fused GAT gather (fp16 H) + softmax + bias + LN + residual + ELU ============
template<int Hh, int C, bool WB16, bool POOL>
__global__ __launch_bounds__(256) void k_gat(
        const __half* __restrict__ H, const float* __restrict__ R,
        const float* __restrict__ bias, const float* __restrict__ gam,
        const float* __restrict__ bet,
        __half* __restrict__ Aout,
        const int* __restrict__ batch, float* __restrict__ out) {
    constexpr int D = Hh * C;
    constexpr int FPL = D / 32;           // 8 or 4

    int n = blockIdx.x * (blockDim.x >> 5) + (threadIdx.x >> 5);
    if (n >= Nn) return;
    int lane = threadIdx.x & 31;
    const int j0 = lane * FPL;
    const int head = j0 / C;

    float adst_l = (lane < Hh) ? g_adst[n * Hh + lane] : 0.f;
    float denom_l = 0.f;
    float acc[FPL];
#pragma unroll
    for (int q = 0; q < FPL; q++) acc[q] = 0.f;

    int beg = g_off[n];
    int deg = g_deg[n];
    int s_next = (deg > 0) ? g_srcs[beg] : n;

    for (int e = 0; e <= deg; e++) {
        int s = s_next;
        s_next = (e + 1 < deg) ? g_srcs[beg + e + 1] : n;
        float w_l = 0.f;
        if (lane < Hh) {
            float ev = lrelu(g_asrc[s * Hh + lane] + adst_l);
            w_l = __expf(ev);
            denom_l += w_l;
        }
        float wj = __shfl_sync(0xFFFFFFFFu, w_l, head);
        const __half* hp = H + (size_t)s * D + j0;
        if (FPL == 8) {
            uint4 hv = *reinterpret_cast<const uint4*>(hp);
            float2 q0 = __half22float2(*reinterpret_cast<__half2*>(&hv.x));
            float2 q1 = __half22float2(*reinterpret_cast<__half2*>(&hv.y));
            float2 q2 = __half22float2(*reinterpret_cast<__half2*>(&hv.z));
            float2 q3 = __half22float2(*reinterpret_cast<__half2*>(&hv.w));
            acc[0] = fmaf(wj, q0.x, acc[0]); acc[1] = fmaf(wj, q0.y, acc[1]);
            acc[2] = fmaf(wj, q1.x, acc[2]); acc[3] = fmaf(wj, q1.y, acc[3]);
            acc[4] = fmaf(wj, q2.x, acc[4]); acc[5] = fmaf(wj, q2.y, acc[5]);
            acc[6] = fmaf(wj, q3.x, acc[6]); acc[7] = fmaf(wj, q3.y, acc[7]);
        } else {
            uint2 hv = *reinterpret_cast<const uint2*>(hp);
            float2 q0 = __half22float2(*reinterpret_cast<__half2*>(&hv.x));
            float2 q1 = __half22float2(*reinterpret_cast<__half2*>(&hv.y));
            acc[0] = fmaf(wj, q0.x, acc[0]); acc[1] = fmaf(wj, q0.y, acc[1]);
            acc[2] = fmaf(wj, q1.x, acc[2]); acc[3] = fmaf(wj, q1.y, acc[3]);
        }
    }

    float dj = __shfl_sync(0xFFFFFFFFu, denom_l, head) + 1e-16f;
    float inv = 1.0f / dj;

    float vals[FPL];
    float s1 = 0.f, s2 = 0.f;
#pragma unroll
    for (int q = 0; q < FPL; q++) {
        float v = fmaf(acc[q], inv, bias[j0 + q]);
        vals[q] = v;
        s1 += v;
        s2 = fmaf(v, v, s2);
    }
#pragma unroll
    for (int o = 16; o > 0; o >>= 1) {
        s1 += __shfl_xor_sync(0xFFFFFFFFu, s1, o);
        s2 += __shfl_xor_sync(0xFFFFFFFFu, s2, o);
    }
    float mean = s1 / (float)D;
    float var = s2 / (float)D - mean * mean;
    float rinv = rsqrtf(var + 1e-5f);

    float o_[FPL];
#pragma unroll
    for (int q = 0; q < FPL; q++) {
        float xv = (vals[q] - mean) * rinv * gam[j0 + q] + bet[j0 + q] + R[(size_t)n * D + j0 + q];
        o_[q] = xv > 0.f ? xv : expm1f(xv);
    }

    if (WB16) {
        __half2* OA = reinterpret_cast<__half2*>(Aout + (size_t)n * D + j0);
#pragma unroll
        for (int q = 0; q < FPL / 2; q++)
            OA[q] = __floats2half2_rn(o_[2 * q], o_[2 * q + 1]);
    } else if (POOL) {
        int b = batch[n];
        red4(&out[b * 128 + j0], make_float4(o_[0], o_[1], o_[2], o_[3]));
        if (lane == 0) atomicAdd(&g_cnt[b], 1.0f);
    }
}

// =========================== pooling finalize ===========================
__global__ void k_pool_zero(float* __restrict__ out) {
    int idx = blockIdx.x * blockDim.x + threadIdx.x;
    if (idx < Gg * 128) out[idx] = 0.f;
    if (idx < Gg) g_cnt[idx] = 0.f;
}
__global__ void k_pool_div(float* __restrict__ out) {
    int idx = blockIdx.x * blockDim.x + threadIdx.x;
    if (idx >= Gg * 128) return;
    out[idx] /= fmaxf(g_cnt[idx >> 7], 1.0f);
}

// =========================== host ===========================
extern "C" void kernel_launch(void* const* d_in, const int* in_sizes, int n_in,
                              void* d_out, int out_size) {
    const float* x   = (const float*)d_in[0];
    const int* ei    = (const int*)d_in[1];
    const int* batch = (const int*)d_in[2];
    const float* W1 = (const float*)d_in[3],  *as1 = (const float*)d_in[4],
               *ad1 = (const float*)d_in[5],  *b1  = (const float*)d_in[6],
               *g1  = (const float*)d_in[7],  *be1 = (const float*)d_in[8],
               *pw1 = (const float*)d_in[9],  *pb1 = (const float*)d_in[10];
    const float* W2 = (const float*)d_in[11], *as2 = (const float*)d_in[12],
               *ad2 = (const float*)d_in[13], *b2  = (const float*)d_in[14],
               *g2  = (const float*)d_in[15], *be2 = (const float*)d_in[16],
               *pw2 = (const float*)d_in[17], *pb2 = (const float*)d_in[18];
    const float* W3 = (const float*)d_in[19], *as3 = (const float*)d_in[20],
               *ad3 = (const float*)d_in[21], *b3  = (const float*)d_in[22],
               *g3  = (const float*)d_in[23], *be3 = (const float*)d_in[24],
               *pw3 = (const float*)d_in[25], *pb3 = (const float*)d_in[26];
    float* out = (float*)d_out;

    void *pH_, *pR_, *pA_, *pB_;
    cudaGetSymbolAddress(&pH_, g_H);
    cudaGetSymbolAddress(&pR_, g_R);
    cudaGetSymbolAddress(&pA_, g_A);
    cudaGetSymbolAddress(&pB_, g_B);
    __half* pH = (__half*)pH_;
    float* pR  = (float*)pR_;
    __half* pA = (__half*)pA_;
    __half* pB = (__half*)pB_;

    cudaFuncSetAttribute(k_hgemm, cudaFuncAttributeMaxDynamicSharedMemorySize, 2 * STAGE_BYTES);

    static cudaStream_t s2 = nullptr;
    static cudaEvent_t evFork = nullptr, evSide = nullptr;
    if (!s2) {
        cudaStreamCreateWithFlags(&s2, cudaStreamNonBlocking);
        cudaEventCreateWithFlags(&evFork, cudaEventDisableTiming);
        cudaEventCreateWithFlags(&evSide, cudaEventDisableTiming);
    }

    const int TB = 256;
    const int MT = (Nn + 127) / 128;

    // ---- fork: side stream does CSR build + prepack L2/L3 + pool zero ----
    cudaEventRecord(evFork, 0);
    cudaStreamWaitEvent(s2, evFork, 0);

    k_zero_deg<<<(Nn + TB - 1) / TB, TB, 0, s2>>>();
    k_hist<<<(Ee + TB - 1) / TB, TB, 0, s2>>>(ei);
    k_scan1<<<NSCAN_BLK, 256, 0, s2>>>();
    k_scan2<<<1, 256, 0, s2>>>();
    k_scan3<<<(Nn + TB - 1) / TB, TB, 0, s2>>>();
    k_scatter<<<(Ee + TB - 1) / TB, TB, 0, s2>>>(ei);
    k_prepack<<<(2 * 128 * 256 + TB - 1) / TB, TB, 0, s2>>>(W2, pw2, 256, 128, BOFF2);
    k_prepack<<<(2 * 128 * 128 + TB - 1) / TB, TB, 0, s2>>>(W3, pw3, 128, 128, BOFF3);
    k_pool_zero<<<(Gg * 128 + TB - 1) / TB, TB, 0, s2>>>(out);
    cudaEventRecord(evSide, s2);

    // ---- main stream: layer 1 ----
    k_cvt_pre<<<(CVT4_L1 + 512 * 128 + TB - 1) / TB, TB>>>(x, pA, W1, pw1);
    k_hgemm<<<dim3(4, MT), 256, 2 * STAGE_BYTES>>>(pA, pB + BOFF1,
                                                   pb1, pH, pR, as1, ad1, 128, 256, 8);

    cudaStreamWaitEvent(0, evSide, 0);

    k_gat<8, 32, true, false><<<(Nn * 32 + TB - 1) / TB, TB>>>(pH, pR, b1, g1, be1,
                                                               pA, nullptr, nullptr);

    // ---- Layer 2 ----
    k_hgemm<<<dim3(2, MT), 256, 2 * STAGE_BYTES>>>(pA, pB + BOFF2,
                                                   pb2, pH, pR, as2, ad2, 256, 128, 4);
    k_gat<4, 32, true, false><<<(Nn * 32 + TB - 1) / TB, TB>>>(pH, pR, b2, g2, be2,
                                                               pA, nullptr, nullptr);

    // ---- Layer 3 ----
    k_hgemm<<<dim3(2, MT), 256, 2 * STAGE_BYTES>>>(pA, pB + BOFF3,
                                                   pb3, pH, pR, as3, ad3, 128, 128, -1);
    k_gat<1, 128, false, true><<<(Nn * 32 + TB - 1) / TB, TB>>>(pH, pR, b3, g3, be3,
                                                                nullptr, batch, out);

    k_pool_div<<<(Gg * 128 + TB - 1) / TB, TB>>>(out);
}

// round 12
// speedup vs baseline: 1.3649x; 1.0234x over previous
#include <cuda_runtime.h>
#include <cuda_bf16.h>
#include <cuda_fp16.h>
#include <math.h>
#include <stdint.h>

#define Nn 50000
#define Ee 800000
#define Gg 512
#define NSCAN_BLK 196          // ceil(50000/256)

// weight pack region offsets (elements)
#define BOFF1 0          // L1: 512 x 128
#define BOFF2 65536      // L2: 256 x 256
#define BOFF3 131072     // L3: 256 x 128
#define BTOT  163840

// ---------------- scratch ----------------
__device__ __align__(256) __half g_H[Nn * 256];    // GAT features, fp16
__device__ __align__(256) __half g_R[Nn * 256];    // residual, fp16
__device__ __align__(256) float g_asrc[Nn * 8];
__device__ __align__(256) float g_adst[Nn * 8];
__device__ __align__(256) float g_cnt[Gg];
// fp16 activations (GEMM A) + fp16 weights
__device__ __align__(256) __half g_A[Nn * 256];
__device__ __align__(256) __half g_B[BTOT];
// CSR
__device__ int g_deg[Nn];
__device__ int g_off[Nn];
__device__ int g_cur[Nn];
__device__ int g_srcs[Ee];
__device__ int g_bsum[256];

__device__ __forceinline__ float lrelu(float x) { return x > 0.0f ? x : 0.2f * x; }
__device__ __forceinline__ void red4(float* p, float4 v) {
    atomicAdd(reinterpret_cast<float4*>(p), v);
}

// =========================== CSR build ===========================
__global__ void k_zero_deg() {
    int i = blockIdx.x * blockDim.x + threadIdx.x;
    if (i < Nn) g_deg[i] = 0;
}
__global__ void k_hist(const int* __restrict__ ei) {
    int e = blockIdx.x * blockDim.x + threadIdx.x;
    if (e < Ee) atomicAdd(&g_deg[ei[Ee + e]], 1);
}
__global__ void k_scan1() {
    __shared__ int sh[256];
    int tid = threadIdx.x;
    int i = blockIdx.x * 256 + tid;
    int v = (i < Nn) ? g_deg[i] : 0;
    sh[tid] = v; __syncthreads();
    for (int off = 1; off < 256; off <<= 1) {
        int t = (tid >= off) ? sh[tid - off] : 0;
        __syncthreads();
        sh[tid] += t;
        __syncthreads();
    }
    if (i < Nn) g_off[i] = sh[tid] - v;
    if (tid == 255) g_bsum[blockIdx.x] = sh[255];
}
__global__ void k_scan2() {
    __shared__ int sh[256];
    int tid = threadIdx.x;
    int v = (tid < NSCAN_BLK) ? g_bsum[tid] : 0;
    sh[tid] = v; __syncthreads();
    for (int off = 1; off < 256; off <<= 1) {
        int t = (tid >= off) ? sh[tid - off] : 0;
        __syncthreads();
        sh[tid] += t;
        __syncthreads();
    }
    if (tid < NSCAN_BLK) g_bsum[tid] = sh[tid] - v;
}
__global__ void k_scan3() {
    int i = blockIdx.x * blockDim.x + threadIdx.x;
    if (i < Nn) {
        g_off[i] += g_bsum[i >> 8];
        g_cur[i] = 0;
    }
}
__global__ void k_scatter(const int* __restrict__ ei) {
    int e = blockIdx.x * blockDim.x + threadIdx.x;
    if (e >= Ee) return;
    int d = ei[Ee + e];
    int pos = g_off[d] + atomicAdd(&g_cur[d], 1);
    g_srcs[pos] = ei[e];
}

// =========== fused: fp32->fp16 cvt of x  +  prepack of layer-1 weights ===========
#define CVT4_L1 (Nn * 128 / 4)
__global__ void k_cvt_pre(const float* __restrict__ X, __half* __restrict__ A,
                          const float* __restrict__ W, const float* __restrict__ pw) {
    int idx = blockIdx.x * blockDim.x + threadIdx.x;
    if (idx < CVT4_L1) {
        float4 v = reinterpret_cast<const float4*>(X)[idx];
        __half2* H2 = reinterpret_cast<__half2*>(A);
        H2[idx * 2]     = __floats2half2_rn(v.x, v.y);
        H2[idx * 2 + 1] = __floats2half2_rn(v.z, v.w);
    } else {
        int j = idx - CVT4_L1;                 // 0 .. 512*128-1
        if (j < 512 * 128) {
            const int K = 128, Dhalf = 256;
            int n = j / K, k = j - n * K;
            float w = (n < Dhalf) ? W[(size_t)k * Dhalf + n]
                                  : pw[(size_t)k * Dhalf + (n - Dhalf)];
            g_B[BOFF1 + j] = __float2half_rn(w);
        }
    }
}

// prepack (layers 2/3, on side stream)
__global__ void k_prepack(const float* __restrict__ W, const float* __restrict__ pw,
                          int K, int Dhalf, int boff) {
    int idx = blockIdx.x * blockDim.x + threadIdx.x;
    int Ncat = 2 * Dhalf;
    if (idx >= Ncat * K) return;
    int n = idx / K, k = idx - n * K;
    float w = (n < Dhalf) ? W[(size_t)k * Dhalf + n] : pw[(size_t)k * Dhalf + (n - Dhalf)];
    g_B[boff + idx] = __float2half_rn(w);
}

// ================ HMMA GEMM (fp16, 3-stage cp.async pipeline + ldmatrix) ================
#define SROW 40
#define STAGE_BYTES 20480
#define NSTAGE 3
#define OFF_A 0
#define OFF_B 10240

__device__ __forceinline__ void mma16816(float* d, const uint32_t* a, const uint32_t* b) {
    asm volatile(
        "mma.sync.aligned.m16n8k16.row.col.f32.f16.f16.f32 "
        "{%0,%1,%2,%3}, {%4,%5,%6,%7}, {%8,%9}, {%0,%1,%2,%3};"
        : "+f"(d[0]), "+f"(d[1]), "+f"(d[2]), "+f"(d[3])
        : "r"(a[0]), "r"(a[1]), "r"(a[2]), "r"(a[3]), "r"(b[0]), "r"(b[1]));
}

__device__ __forceinline__ void ldsm4(uint32_t* r, uint32_t addr) {
    asm volatile("ldmatrix.sync.aligned.m8n8.x4.shared.b16 {%0,%1,%2,%3}, [%4];"
                 : "=r"(r[0]), "=r"(r[1]), "=r"(r[2]), "=r"(r[3]) : "r"(addr));
}

__device__ __forceinline__ uint32_t smem_u32(const void* p) {
    uint32_t a;
    asm("{ .reg .u64 t; cvta.to.shared.u64 t, %1; cvt.u32.u64 %0, t; }" : "=r"(a) : "l"(p));
    return a;
}

__device__ __forceinline__ void cp16(uint32_t dst, const void* src, bool ok) {
    asm volatile(
        "{\n\t.reg .pred p;\n\tsetp.ne.u32 p, %2, 0;\n\t"
        "@p cp.async.cg.shared.global [%0], [%1], 16;\n\t"
        "@!p cp.async.cg.shared.global [%0], [%1], 16, 0;\n\t}"
        :: "r"(dst), "l"(src), "r"((unsigned)ok) : "memory");
}

// Hh > 0 : C=32 fused per-head scores; Hh == -1: layer-3 scores via smem reduce
__global__ __launch_bounds__(256) void k_hgemm(
        const __half* __restrict__ A, const __half* __restrict__ B,
        const float* __restrict__ pb, __half* __restrict__ Hout, __half* __restrict__ Rout,
        const float* __restrict__ asv, const float* __restrict__ adv,
        int K, int Dhalf, int Hh) {
    extern __shared__ __align__(16) char smem[];
    const uint32_t sbase = smem_u32(smem);

    const int tid = threadIdx.x;
    const int wid = tid >> 5, lane = tid & 31;
    const int row0 = blockIdx.y * 128;
    const int n0 = blockIdx.x * 128;
    const int KC = K >> 5;        // 4 or 8 (always >= 3)
    const int wr = wid >> 2;
    const int wc = wid & 3;
    const int tr = lane >> 2;
    const int tc = (lane & 3) * 2;

    const int lr = tid >> 2;
    const int lk = (tid & 3) * 8;

    const uint32_t a_base = (uint32_t)(((wr * 64 + (lane & 15)) * SROW + (lane >> 4) * 8) * 2);
    const int bt = lane >> 3;
    const uint32_t b_base = (uint32_t)((((wc * 32 + (bt >> 1) * 8 + (lane & 7))) * SROW + (bt & 1) * 8) * 2);

    float acc[4][4][4];
#pragma unroll
    for (int mi = 0; mi < 4; mi++)
#pragma unroll
        for (int ni = 0; ni < 4; ni++)
#pragma unroll
            for (int q = 0; q < 4; q++) acc[mi][ni][q] = 0.f;

    auto load_stage = [&](int stage, int kc) {
        const uint32_t sb = sbase + stage * STAGE_BYTES;
        const int kofs = kc * 32 + lk;
#pragma unroll
        for (int it = 0; it < 2; it++) {
            int r = lr + it * 64;
            uint32_t so = (uint32_t)(r * SROW + lk) * 2;
            int ar = row0 + r;
            bool ok = ar < Nn;
            int arc = ok ? ar : 0;
            cp16(sb + OFF_A + so, A + (size_t)arc * K + kofs, ok);
            cp16(sb + OFF_B + so, B + (size_t)(n0 + r) * K + kofs, true);
        }
        asm volatile("cp.async.commit_group;" ::: "memory");
    };

    // prologue: 2 stages in flight
    load_stage(0, 0);
    load_stage(1, 1);

    for (int kc = 0; kc < KC; kc++) {
        // wait for stage kc's group (leave 1 outstanding mid-loop, 0 at end)
        if (kc < KC - 1)
            asm volatile("cp.async.wait_group 1;" ::: "memory");
        else
            asm volatile("cp.async.wait_group 0;" ::: "memory");
        __syncthreads();   // stage-kc data visible; everyone done with stage being overwritten next

        if (kc + 2 < KC) load_stage((kc + 2) % NSTAGE, kc + 2);

        const uint32_t sb = sbase + (kc % NSTAGE) * STAGE_BYTES;

#pragma unroll
        for (int ks = 0; ks < 2; ks++) {
            const uint32_t kbB = (uint32_t)(ks * 16 * 2);
            uint32_t a_f[4][4], bh[8];
#pragma unroll
            for (int p = 0; p < 2; p++)
                ldsm4(bh + p * 4, sb + OFF_B + b_base + p * (16 * SROW * 2) + kbB);
#pragma unroll
            for (int mi = 0; mi < 4; mi++)
                ldsm4(a_f[mi], sb + OFF_A + a_base + mi * (16 * SROW * 2) + kbB);
#pragma unroll
            for (int mi = 0; mi < 4; mi++)
#pragma unroll
                for (int ni = 0; ni < 4; ni++)
                    mma16816(acc[mi][ni], a_f[mi], bh + ni * 2);
        }
    }

    const bool isR = (n0 >= Dhalf);
    const int cbase = (isR ? (n0 - Dhalf) : n0) + wc * 32;
#pragma unroll
    for (int mi = 0; mi < 4; mi++) {
        int r1 = row0 + wr * 64 + mi * 16 + tr;
        int r2 = r1 + 8;
#pragma unroll
        for (int ni = 0; ni < 4; ni++) {
            int cc = cbase + ni * 8 + tc;
            if (isR) {
                float bx = pb[cc], by = pb[cc + 1];
                if (r1 < Nn)
                    *reinterpret_cast<__half2*>(Rout + (size_t)r1 * Dhalf + cc) =
                        __floats2half2_rn(acc[mi][ni][0] + bx, acc[mi][ni][1] + by);
                if (r2 < Nn)
                    *reinterpret_cast<__half2*>(Rout + (size_t)r2 * Dhalf + cc) =
                        __floats2half2_rn(acc[mi][ni][2] + bx, acc[mi][ni][3] + by);
            } else {
                if (r1 < Nn)
                    *reinterpret_cast<__half2*>(Hout + (size_t)r1 * Dhalf + cc) =
                        __floats2half2_rn(acc[mi][ni][0], acc[mi][ni][1]);
                if (r2 < Nn)
                    *reinterpret_cast<__half2*>(Hout + (size_t)r2 * Dhalf + cc) =
                        __floats2half2_rn(acc[mi][ni][2], acc[mi][ni][3]);
            }
        }
    }

    // ---- fused attention scores (from fp32 accumulators) ----
    if (Hh != 0 && !isR) {
        const float* as_sl = asv + n0 + wc * 32;
        const float* ad_sl = adv + n0 + wc * 32;
        float as_c[8], ad_c[8];
#pragma unroll
        for (int ni = 0; ni < 4; ni++) {
            int c0 = ni * 8 + tc;
            as_c[ni * 2]     = as_sl[c0];
            as_c[ni * 2 + 1] = as_sl[c0 + 1];
            ad_c[ni * 2]     = ad_sl[c0];
            ad_c[ni * 2 + 1] = ad_sl[c0 + 1];
        }
        float* sAS = reinterpret_cast<float*>(smem);
        float* sAD = reinterpret_cast<float*>(smem) + 128;
        if (Hh < 0) {
            __syncthreads();   // smem region aliases pipeline stage 0 — drain mainloop readers
            if (tid < 128) { sAS[tid] = 0.f; sAD[tid] = 0.f; }
            __syncthreads();
        }
#pragma unroll
        for (int mi = 0; mi < 4; mi++) {
            int lrow1 = wr * 64 + mi * 16 + tr;
            int lrow2 = lrow1 + 8;
            float as1 = 0.f, ad1 = 0.f, as2 = 0.f, ad2 = 0.f;
#pragma unroll
            for (int ni = 0; ni < 4; ni++) {
                as1 = fmaf(acc[mi][ni][0], as_c[ni * 2], fmaf(acc[mi][ni][1], as_c[ni * 2 + 1], as1));
                ad1 = fmaf(acc[mi][ni][0], ad_c[ni * 2], fmaf(acc[mi][ni][1], ad_c[ni * 2 + 1], ad1));
                as2 = fmaf(acc[mi][ni][2], as_c[ni * 2], fmaf(acc[mi][ni][3], as_c[ni * 2 + 1], as2));
                ad2 = fmaf(acc[mi][ni][2], ad_c[ni * 2], fmaf(acc[mi][ni][3], ad_c[ni * 2 + 1], ad2));
            }
#pragma unroll
            for (int o = 1; o < 4; o <<= 1) {
                as1 += __shfl_xor_sync(0xFFFFFFFFu, as1, o);
                ad1 += __shfl_xor_sync(0xFFFFFFFFu, ad1, o);
                as2 += __shfl_xor_sync(0xFFFFFFFFu, as2, o);
                ad2 += __shfl_xor_sync(0xFFFFFFFFu, ad2, o);
            }
            if ((lane & 3) == 0) {
                if (Hh > 0) {
                    const int head = (n0 >> 5) + wc;
                    int r1 = row0 + lrow1, r2 = row0 + lrow2;
                    if (r1 < Nn) { g_asrc[r1 * Hh + head] = as1; g_adst[r1 * Hh + head] = ad1; }
                    if (r2 < Nn) { g_asrc[r2 * Hh + head] = as2; g_adst[r2 * Hh + head] = ad2; }
                } else {
                    atomicAdd(&sAS[lrow1], as1); atomicAdd(&sAD[lrow1], ad1);
                    atomicAdd(&sAS[lrow2], as2); atomicAdd(&sAD[lrow2], ad2);
                }
            }
        }
        if (Hh < 0) {
            __syncthreads();
            if (tid < 128 && row0 + tid < Nn) {
                g_asrc[row0 + tid] = sAS[tid];
                g_adst[row0 + tid] = sAD[tid];
            }
        }
    }
}

// ============ fused GAT gather (fp16 H) + softmax + bias + LN + residual(fp16) + ELU ============
template<int Hh, int C, bool WB16, bool POOL>
__global__ __launch_bounds__(256) void k_gat(
        const __half* __restrict__ H, const __half* __restrict__ R,
        const float* __restrict__ bias, const float* __restrict__ gam,
        const float* __restrict__ bet,
        __half* __restrict__ Aout,
        const int* __restrict__ batch, float* __restrict__ out) {
    constexpr int D = Hh * C;
    constexpr int FPL = D / 32;           // 8 or 4

    int n = blockIdx.x * (blockDim.x >> 5) + (threadIdx.x >> 5);
    if (n >= Nn) return;
    int lane = threadIdx.x & 31;
    const int j0 = lane * FPL;
    const int head = j0 / C;

    float adst_l = (lane < Hh) ? g_adst[n * Hh + lane] : 0.f;
    float denom_l = 0.f;
    float acc[FPL];
#pragma unroll
    for (int q = 0; q < FPL; q++) acc[q] = 0.f;

    int beg = g_off[n];
    int deg = g_deg[n];
    int s_next = (deg > 0) ? g_srcs[beg] : n;

    for (int e = 0; e <= deg; e++) {
        int s = s_next;
        s_next = (e + 1 < deg) ? g_srcs[beg + e + 1] : n;
        float w_l = 0.f;
        if (lane < Hh) {
            float ev = lrelu(g_asrc[s * Hh + lane] + adst_l);
            w_l = __expf(ev);
            denom_l += w_l;
        }
        float wj = __shfl_sync(0xFFFFFFFFu, w_l, head);
        const __half* hp = H + (size_t)s * D + j0;
        if (FPL == 8) {
            uint4 hv = *reinterpret_cast<const uint4*>(hp);
            float2 q0 = __half22float2(*reinterpret_cast<__half2*>(&hv.x));
            float2 q1 = __half22float2(*reinterpret_cast<__half2*>(&hv.y));
            float2 q2 = __half22float2(*reinterpret_cast<__half2*>(&hv.z));
            float2 q3 = __half22float2(*reinterpret_cast<__half2*>(&hv.w));
            acc[0] = fmaf(wj, q0.x, acc[0]); acc[1] = fmaf(wj, q0.y, acc[1]);
            acc[2] = fmaf(wj, q1.x, acc[2]); acc[3] = fmaf(wj, q1.y, acc[3]);
            acc[4] = fmaf(wj, q2.x, acc[4]); acc[5] = fmaf(wj, q2.y, acc[5]);
            acc[6] = fmaf(wj, q3.x, acc[6]); acc[7] = fmaf(wj, q3.y, acc[7]);
        } else {
            uint2 hv = *reinterpret_cast<const uint2*>(hp);
            float2 q0 = __half22float2(*reinterpret_cast<__half2*>(&hv.x));
            float2 q1 = __half22float2(*reinterpret_cast<__half2*>(&hv.y));
            acc[0] = fmaf(wj, q0.x, acc[0]); acc[1] = fmaf(wj, q0.y, acc[1]);
            acc[2] = fmaf(wj, q1.x, acc[2]); acc[3] = fmaf(wj, q1.y, acc[3]);
        }
    }

    float dj = __shfl_sync(0xFFFFFFFFu, denom_l, head) + 1e-16f;
    float inv = 1.0f / dj;

    float vals[FPL];
    float s1 = 0.f, s2 = 0.f;
#pragma unroll
    for (int q = 0; q < FPL; q++) {
        float v = fmaf(acc[q], inv, bias[j0 + q]);
        vals[q] = v;
        s1 += v;
        s2 = fmaf(v, v, s2);
    }
#pragma unroll
    for (int o = 16; o > 0; o >>= 1) {
        s1 += __shfl_xor_sync(0xFFFFFFFFu, s1, o);
        s2 += __shfl_xor_sync(0xFFFFFFFFu, s2, o);
    }
    float mean = s1 / (float)D;
    float var = s2 / (float)D - mean * mean;
    float rinv = rsqrtf(var + 1e-5f);

    // fp16 residual, vector load
    float rres[FPL];
    {
        const __half* rp = R + (size_t)n * D + j0;
        if (FPL == 8) {
            uint4 rv = *reinterpret_cast<const uint4*>(rp);
            float2 r0 = __half22float2(*reinterpret_cast<__half2*>(&rv.x));
            float2 r1 = __half22float2(*reinterpret_cast<__half2*>(&rv.y));
            float2 r2 = __half22float2(*reinterpret_cast<__half2*>(&rv.z));
            float2 r3 = __half22float2(*reinterpret_cast<__half2*>(&rv.w));
            rres[0] = r0.x; rres[1] = r0.y; rres[2] = r1.x; rres[3] = r1.y;
            rres[4] = r2.x; rres[5] = r2.y; rres[6] = r3.x; rres[7] = r3.y;
        } else {
            uint2 rv = *reinterpret_cast<const uint2*>(rp);
            float2 r0 = __half22float2(*reinterpret_cast<__half2*>(&rv.x));
            float2 r1 = __half22float2(*reinterpret_cast<__half2*>(&rv.y));
            rres[0] = r0.x; rres[1] = r0.y; rres[2] = r1.x; rres[3] = r1.y;
        }
    }

    float o_[FPL];
#pragma unroll
    for (int q = 0; q < FPL; q++) {
        float xv = (vals[q] - mean) * rinv * gam[j0 + q] + bet[j0 + q] + rres[q];
        o_[q] = xv > 0.f ? xv : expm1f(xv);
    }

    if (WB16) {
        __half2* OA = reinterpret_cast<__half2*>(Aout + (size_t)n * D + j0);
#pragma unroll
        for (int q = 0; q < FPL / 2; q++)
            OA[q] = __floats2half2_rn(o_[2 * q], o_[2 * q + 1]);
    } else if (POOL) {
        int b = batch[n];
        red4(&out[b * 128 + j0], make_float4(o_[0], o_[1], o_[2], o_[3]));
        if (lane == 0) atomicAdd(&g_cnt[b], 1.0f);
    }
}

// =========================== pooling finalize ===========================
__global__ void k_pool_zero(float* __restrict__ out) {
    int idx = blockIdx.x * blockDim.x + threadIdx.x;
    if (idx < Gg * 128) out[idx] = 0.f;
    if (idx < Gg) g_cnt[idx] = 0.f;
}
__global__ void k_pool_div(float* __restrict__ out) {
    int idx = blockIdx.x * blockDim.x + threadIdx.x;
    if (idx >= Gg * 128) return;
    out[idx] /= fmaxf(g_cnt[idx >> 7], 1.0f);
}

// =========================== host ===========================
extern "C" void kernel_launch(void* const* d_in, const int* in_sizes, int n_in,
                              void* d_out, int out_size) {
    const float* x   = (const float*)d_in[0];
    const int* ei    = (const int*)d_in[1];
    const int* batch = (const int*)d_in[2];
    const float* W1 = (const float*)d_in[3],  *as1 = (const float*)d_in[4],
               *ad1 = (const float*)d_in[5],  *b1  = (const float*)d_in[6],
               *g1  = (const float*)d_in[7],  *be1 = (const float*)d_in[8],
               *pw1 = (const float*)d_in[9],  *pb1 = (const float*)d_in[10];
    const float* W2 = (const float*)d_in[11], *as2 = (const float*)d_in[12],
               *ad2 = (const float*)d_in[13], *b2  = (const float*)d_in[14],
               *g2  = (const float*)d_in[15], *be2 = (const float*)d_in[16],
               *pw2 = (const float*)d_in[17], *pb2 = (const float*)d_in[18];
    const float* W3 = (const float*)d_in[19], *as3 = (const float*)d_in[20],
               *ad3 = (const float*)d_in[21], *b3  = (const float*)d_in[22],
               *g3  = (const float*)d_in[23], *be3 = (const float*)d_in[24],
               *pw3 = (const float*)d_in[25], *pb3 = (const float*)d_in[26];
    float* out = (float*)d_out;

    void *pH_, *pR_, *pA_, *pB_;
    cudaGetSymbolAddress(&pH_, g_H);
    cudaGetSymbolAddress(&pR_, g_R);
    cudaGetSymbolAddress(&pA_, g_A);
    cudaGetSymbolAddress(&pB_, g_B);
    __half* pH = (__half*)pH_;
    __half* pR = (__half*)pR_;
    __half* pA = (__half*)pA_;
    __half* pB = (__half*)pB_;

    cudaFuncSetAttribute(k_hgemm, cudaFuncAttributeMaxDynamicSharedMemorySize,
                         NSTAGE * STAGE_BYTES);

    static cudaStream_t s2 = nullptr;
    static cudaEvent_t evFork = nullptr, evSide = nullptr;
    if (!s2) {
        cudaStreamCreateWithFlags(&s2, cudaStreamNonBlocking);
        cudaEventCreateWithFlags(&evFork, cudaEventDisableTiming);
        cudaEventCreateWithFlags(&evSide, cudaEventDisableTiming);
    }

    const int TB = 256;
    const int MT = (Nn + 127) / 128;

    // ---- fork: side stream does CSR build + prepack L2/L3 + pool zero ----
    cudaEventRecord(evFork, 0);
    cudaStreamWaitEvent(s2, evFork, 0);

    k_zero_deg<<<(Nn + TB - 1) / TB, TB, 0, s2>>>();
    k_hist<<<(Ee + TB - 1) / TB, TB, 0, s2>>>(ei);
    k_scan1<<<NSCAN_BLK, 256, 0, s2>>>();
    k_scan2<<<1, 256, 0, s2>>>();
    k_scan3<<<(Nn + TB - 1) / TB, TB, 0, s2>>>();
    k_scatter<<<(Ee + TB - 1) / TB, TB, 0, s2>>>(ei);
    k_prepack<<<(2 * 128 * 256 + TB - 1) / TB, TB, 0, s2>>>(W2, pw2, 256, 128, BOFF2);
    k_prepack<<<(2 * 128 * 128 + TB - 1) / TB, TB, 0, s2>>>(W3, pw3, 128, 128, BOFF3);
    k_pool_zero<<<(Gg * 128 + TB - 1) / TB, TB, 0, s2>>>(out);
    cudaEventRecord(evSide, s2);

    // ---- main stream: layer 1 ----
    k_cvt_pre<<<(CVT4_L1 + 512 * 128 + TB - 1) / TB, TB>>>(x, pA, W1, pw1);
    k_hgemm<<<dim3(4, MT), 256, NSTAGE * STAGE_BYTES>>>(pA, pB + BOFF1,
                                                        pb1, pH, pR, as1, ad1, 128, 256, 8);

    cudaStreamWaitEvent(0, evSide, 0);

    k_gat<8, 32, true, false><<<(Nn * 32 + TB - 1) / TB, TB>>>(pH, pR, b1, g1, be1,
                                                               pA, nullptr, nullptr);

    // ---- Layer 2 ----
    k_hgemm<<<dim3(2, MT), 256, NSTAGE * STAGE_BYTES>>>(pA, pB + BOFF2,
                                                        pb2, pH, pR, as2, ad2, 256, 128, 4);
    k_gat<4, 32, true, false><<<(Nn * 32 + TB - 1) / TB, TB>>>(pH, pR, b2, g2, be2,
                                                               pA, nullptr, nullptr);

    // ---- Layer 3 ----
    k_hgemm<<<dim3(2, MT), 256, NSTAGE * STAGE_BYTES>>>(pA, pB + BOFF3,
                                                        pb3, pH, pR, as3, ad3, 128, 128, -1);
    k_gat<1, 128, false, true><<<(Nn * 32 + TB - 1) / TB, TB>>>(pH, pR, b3, g3, be3,
                                                                nullptr, batch, out);

    k_pool_div<<<(Gg * 128 + TB - 1) / TB, TB>>>(out);
}